// round 13
// baseline (speedup 1.0000x reference)
#include <cuda_runtime.h>

#define BB 64
#define TT 256
#define DD 512
#define HH 512

typedef unsigned long long ull;

// ---------------- scratch (static device allocations only) ----------------
__device__ __align__(16) float g_h0T[2][HH * BB];        // h0 [k][b], double buffered
__device__ __align__(16) float g_o0T[TT][DD * BB];       // o0_t [k][b] history
__device__ __align__(16) float g_h1T[TT][HH * BB];       // g_h1T[t] = h1_{t-1}
__device__ __align__(16) float g_P0[(size_t)TT * BB * 1024]; // x @ W0x
__device__ __align__(16) float g_W0x[DD * 1024];
__device__ __align__(16) float g_W0r[HH * 1024];
__device__ float g_b0[1024];
__device__ unsigned int g_bar;

// ---------------- helpers --------------------------------------------------
__device__ __forceinline__ ull ffma2(ull a, ull b, ull c) {
    ull d; asm("fma.rn.f32x2 %0, %1, %2, %3;" : "=l"(d) : "l"(a), "l"(b), "l"(c));
    return d;
}
__device__ __forceinline__ ull dup2(float x) {
    ull d; asm("mov.b64 %0, {%1, %1};" : "=l"(d) : "f"(x));
    return d;
}
__device__ __forceinline__ float2 unpk(ull a) {
    float2 v; asm("mov.b64 {%0, %1}, %2;" : "=f"(v.x), "=f"(v.y) : "l"(a));
    return v;
}
__device__ __forceinline__ float2 ldcg2(const float* p) {
    float2 v;
    asm volatile("ld.global.cg.v2.f32 {%0,%1}, [%2];" : "=f"(v.x), "=f"(v.y) : "l"(p));
    return v;
}
__device__ __forceinline__ void stcg(float* p, float v) {
    asm volatile("st.global.cg.f32 [%0], %1;" :: "l"(p), "f"(v));
}
__device__ __forceinline__ void cpasync16(unsigned saddr, const float* gptr) {
    asm volatile("cp.async.cg.shared.global [%0], [%1], 16;" :: "r"(saddr), "l"(gptr));
}
__device__ __forceinline__ void cp_commit() {
    asm volatile("cp.async.commit_group;");
}
template <int N>
__device__ __forceinline__ void cp_wait() {
    asm volatile("cp.async.wait_group %0;" :: "n"(N));
}
// Accurate tanh independent of --use_fast_math.
__device__ __forceinline__ float tanh_acc(float x) {
    float ax = fabsf(x);
    float u  = expm1f(-2.0f * ax);
    float r  = -u / (2.0f + u);
    return x >= 0.0f ? r : -r;
}

// ---------------- layer-0 weight packing ----------------------------------
__global__ void pack0(const float* __restrict__ Wh0, const float* __restrict__ Wo0,
                      const float* __restrict__ bh0, const float* __restrict__ bo0)
{
    int idx = blockIdx.x * blockDim.x + threadIdx.x;
    if (idx >= DD * 1024) return;
    int k = idx >> 10, n = idx & 1023;
    bool hc = n < HH;
    int c = hc ? n : n - HH;
    g_W0x[idx] = hc ? Wh0[k * HH + c]        : Wo0[k * DD + c];
    g_W0r[idx] = hc ? Wh0[(DD + k) * HH + c] : Wo0[(DD + k) * DD + c];
    if (idx < 1024) g_b0[idx] = hc ? bh0[c] : bo0[c];
}

__global__ void init_state(const float* __restrict__ enc) {
    int idx = blockIdx.x * blockDim.x + threadIdx.x;
    if (idx < HH * BB) {
        int k = idx >> 6, b = idx & 63;
        g_h0T[0][k * 64 + b] = enc[b * HH + k];
        g_h1T[0][idx] = 0.0f;
    }
    if (idx == 0) g_bar = 0u;
}

// ---------------- GEMM 0: P0[m,0:1024] = x_row(m) @ W0x,  m = t*64+b -------
__global__ __launch_bounds__(256)
void gemm0(const float* __restrict__ x)
{
    __shared__ __align__(16) float2 As2[16][128];
    __shared__ __align__(16) float  Bs[16][128];

    const int tid = threadIdx.x;
    const int m0 = blockIdx.y * 128;
    const int n0 = blockIdx.x * 128;

    const int ai = tid >> 2;
    const int ak = (tid & 3) << 2;
    const int mg0 = m0 + ai, mg1 = m0 + ai + 64;
    const float* ap0 = x + (size_t)(mg0 & 63) * (TT * DD) + (size_t)(mg0 >> 6) * DD + ak;
    const float* ap1 = x + (size_t)(mg1 & 63) * (TT * DD) + (size_t)(mg1 >> 6) * DD + ak;

    const int bk = tid >> 5;
    const int bn = (tid & 31) << 2;
    const float* bp = g_W0x + (size_t)bk * 1024 + n0 + bn;

    const int ty = tid >> 4, tx = tid & 15;

    ull acc[8][4];
#pragma unroll
    for (int i = 0; i < 8; ++i)
#pragma unroll
        for (int j = 0; j < 4; ++j) acc[i][j] = 0ull;

    for (int k0 = 0; k0 < DD; k0 += 16) {
        float4 av0 = *(const float4*)(ap0 + k0);
        float4 av1 = *(const float4*)(ap1 + k0);
        float4 bv0 = *(const float4*)(bp + (size_t)k0 * 1024);
        float4 bv1 = *(const float4*)(bp + (size_t)(k0 + 8) * 1024);
        __syncthreads();
        As2[ak + 0][ai] = make_float2(av0.x, av0.x);
        As2[ak + 1][ai] = make_float2(av0.y, av0.y);
        As2[ak + 2][ai] = make_float2(av0.z, av0.z);
        As2[ak + 3][ai] = make_float2(av0.w, av0.w);
        As2[ak + 0][ai + 64] = make_float2(av1.x, av1.x);
        As2[ak + 1][ai + 64] = make_float2(av1.y, av1.y);
        As2[ak + 2][ai + 64] = make_float2(av1.z, av1.z);
        As2[ak + 3][ai + 64] = make_float2(av1.w, av1.w);
        *(float4*)&Bs[bk][bn]     = bv0;
        *(float4*)&Bs[bk + 8][bn] = bv1;
        __syncthreads();
#pragma unroll
        for (int k = 0; k < 16; ++k) {
            ulonglong2 a01 = *(const ulonglong2*)&As2[k][ty * 8 + 0];
            ulonglong2 a23 = *(const ulonglong2*)&As2[k][ty * 8 + 2];
            ulonglong2 a45 = *(const ulonglong2*)&As2[k][ty * 8 + 4];
            ulonglong2 a67 = *(const ulonglong2*)&As2[k][ty * 8 + 6];
            ulonglong2 b03 = *(const ulonglong2*)&Bs[k][tx * 8 + 0];
            ulonglong2 b47 = *(const ulonglong2*)&Bs[k][tx * 8 + 4];
            ull a[8] = {a01.x, a01.y, a23.x, a23.y, a45.x, a45.y, a67.x, a67.y};
            ull b[4] = {b03.x, b03.y, b47.x, b47.y};
#pragma unroll
            for (int i = 0; i < 8; ++i)
#pragma unroll
                for (int j = 0; j < 4; ++j)
                    acc[i][j] = ffma2(a[i], b[j], acc[i][j]);
        }
    }
#pragma unroll
    for (int i = 0; i < 8; ++i) {
        float* cp = g_P0 + (size_t)(m0 + ty * 8 + i) * 1024 + n0 + tx * 8;
        *(ulonglong2*)cp       = make_ulonglong2(acc[i][0], acc[i][1]);
        *(ulonglong2*)(cp + 4) = make_ulonglong2(acc[i][2], acc[i][3]);
    }
}

// ---------------- fused pipelined scan: 64 fat CTAs -------------------------
// bx < 32  : "A" CTA — 32 cols of [h0|o0], K=512 vs g_h0T
// bx >= 32 : "B" CTA — 16 cols of h1, K=1024 vs [o0_{t-1} | h1_{t-2}]
// Chunk compute (~2050cyc) now exceeds chunk staging (~1100cyc): staging hides.
// Chip L2 traffic halves (12MB/round). Barrier fan-in 64.
// SMEM floats: Ws 16384 | stg0 8192 | stg1 8192 | red 4096 = 144 KB.
__global__ __launch_bounds__(256)
void scan_fused(const float* __restrict__ Wh1, const float* __restrict__ bh1)
{
    extern __shared__ __align__(16) float sm[];
    float* Ws   = sm;            // 16384 floats (64 KB)
    float* stg0 = sm + 16384;    // 8192 floats (32 KB)
    float* stg1 = sm + 24576;    // 8192 floats (32 KB)
    float* red  = sm + 32768;    // 4096 floats (16 KB)

    const int tid = threadIdx.x;
    const int bx  = blockIdx.x;
    const int w   = tid >> 5, ln = tid & 31;
    const int rr  = tid >> 2;
    const int jj  = (tid & 3) << 1;
    const ull* wsq = (const ull*)Ws;
    ull* redq = (ull*)red;

    const unsigned s0addr = (unsigned)__cvta_generic_to_shared(stg0);
    const unsigned s1addr = (unsigned)__cvta_generic_to_shared(stg1);

    if (bx < 32) {
        // ================= A: layer-0, 32 packed cols, K=512 =================
        const int n0 = bx * 32;
        for (int i = tid; i < 512 * 32; i += 256) {
            int k = i >> 5, j = i & 31;
            Ws[i] = g_W0r[k * 1024 + n0 + j];
        }
        float bA0[4], bA1[4];
#pragma unroll
        for (int p = 0; p < 4; ++p) {
            bA0[p] = g_b0[n0 + p * 8 + jj];
            bA1[p] = g_b0[n0 + p * 8 + jj + 1];
        }
        __syncthreads();

        for (int r = 0; r < TT; ++r) {
            float2 pv[4];
#pragma unroll
            for (int p = 0; p < 4; ++p)
                pv[p] = ldcg2(&g_P0[((size_t)r * 64 + rr) * 1024 + n0 + p * 8 + jj]);
            const float* hsrc = g_h0T[r & 1];

            // stage chunk 0 (128 k rows = 32 KB)
#pragma unroll
            for (int i = 0; i < 8; ++i)
                cpasync16(s0addr + (tid + i * 256) * 16, hsrc + (tid + i * 256) * 4);
            cp_commit();

            ull a0[16], a1[16];
#pragma unroll
            for (int q = 0; q < 16; ++q) { a0[q] = 0ull; a1[q] = 0ull; }

#pragma unroll
            for (int c = 0; c < 4; ++c) {
                if (c < 3) {
                    const unsigned dst = (c & 1) ? s0addr : s1addr;
                    const float* src = hsrc + (c + 1) * 8192;
#pragma unroll
                    for (int i = 0; i < 8; ++i)
                        cpasync16(dst + (tid + i * 256) * 16, src + (tid + i * 256) * 4);
                    cp_commit();
                    cp_wait<1>();
                } else {
                    cp_wait<0>();
                }
                __syncthreads();
                const float* hb = (c & 1) ? stg1 : stg0;
                const int kg = c * 128 + w * 16;
#pragma unroll 2
                for (int kk = 0; kk < 16; ++kk) {
                    float2 h2 = *(const float2*)(hb + (w * 16 + kk) * 64 + 2 * ln);
                    ull hx = dup2(h2.x), hy = dup2(h2.y);
                    const ulonglong2* wp = (const ulonglong2*)(wsq + (size_t)(kg + kk) * 16);
#pragma unroll
                    for (int j = 0; j < 8; ++j) {
                        ulonglong2 u = wp[j];
                        a0[2 * j]     = ffma2(hx, u.x, a0[2 * j]);
                        a1[2 * j]     = ffma2(hy, u.x, a1[2 * j]);
                        a0[2 * j + 1] = ffma2(hx, u.y, a0[2 * j + 1]);
                        a1[2 * j + 1] = ffma2(hy, u.y, a1[2 * j + 1]);
                    }
                }
                __syncthreads();
            }

            // four reduce passes of 8 cols each (champion layout)
#pragma unroll
            for (int p = 0; p < 4; ++p) {
#pragma unroll
                for (int q = 0; q < 4; ++q) {
                    redq[(w * 64 + 2 * ln)     * 4 + q] = a0[p * 4 + q];
                    redq[(w * 64 + 2 * ln + 1) * 4 + q] = a1[p * 4 + q];
                }
                __syncthreads();
                float s0 = pv[p].x + bA0[p];
                float s1 = pv[p].y + bA1[p];
#pragma unroll
                for (int ww = 0; ww < 8; ++ww) {
                    float2 t2 = *(const float2*)&red[(ww * 64 + rr) * 8 + jj];
                    s0 += t2.x; s1 += t2.y;
                }
                s0 = tanh_acc(s0);
                s1 = tanh_acc(s1);
                const int c = n0 + p * 8 + jj;
                if (n0 < 512) {
                    float* dst = g_h0T[(r + 1) & 1];
                    stcg(dst + (c)     * 64 + rr, s0);
                    stcg(dst + (c + 1) * 64 + rr, s1);
                } else {
                    float* dst = g_o0T[r];
                    stcg(dst + (c - 512) * 64 + rr, s0);
                    stcg(dst + (c - 511) * 64 + rr, s1);
                }
                __syncthreads();
            }
            if (r < TT - 1) {
                if (tid == 0) {
                    asm volatile("red.release.gpu.global.add.u32 [%0], 1;"
                                 :: "l"(&g_bar) : "memory");
                    const unsigned tgt = (unsigned)(r + 1) * 64u;
                    unsigned v;
                    do {
                        asm volatile("ld.acquire.gpu.global.u32 %0, [%1];"
                                     : "=r"(v) : "l"(&g_bar) : "memory");
                    } while (v < tgt);
                }
                __syncthreads();
            }
        }
    } else {
        // ================= B: layer-1 hidden chain, 16 cols, K=1024 ==========
        const int c0 = (bx - 32) * 16;
        for (int i = tid; i < 1024 * 16; i += 256) {
            int k = i >> 4, j = i & 15;
            Ws[i] = Wh1[k * 512 + c0 + j];
        }
        float bB0[2], bB1[2];
#pragma unroll
        for (int p = 0; p < 2; ++p) {
            bB0[p] = bh1[c0 + p * 8 + jj];
            bB1[p] = bh1[c0 + p * 8 + jj + 1];
        }
        __syncthreads();

        for (int r = 0; r < TT; ++r) {
            if (r >= 1) {
                const int t1 = r - 1;
                const float* srcA = g_o0T[t1];   // k in [0, 512)
                const float* srcH = g_h1T[t1];   // k in [512, 1024)

                // stage chunk 0 (32 KB) into stg0
#pragma unroll
                for (int i = 0; i < 8; ++i)
                    cpasync16(s0addr + (tid + i * 256) * 16, srcA + (tid + i * 256) * 4);
                cp_commit();

                ull a0[8], a1[8];
#pragma unroll
                for (int q = 0; q < 8; ++q) { a0[q] = 0ull; a1[q] = 0ull; }

#pragma unroll
                for (int c = 0; c < 8; ++c) {
                    if (c < 7) {
                        const int cn = c + 1;
                        const float* src = (cn < 4) ? (srcA + cn * 8192)
                                                    : (srcH + (cn - 4) * 8192);
                        const unsigned dst = (cn & 1) ? s1addr : s0addr;
#pragma unroll
                        for (int i = 0; i < 8; ++i)
                            cpasync16(dst + (tid + i * 256) * 16,
                                      src + (tid + i * 256) * 4);
                        cp_commit();
                        cp_wait<1>();
                    } else {
                        cp_wait<0>();
                    }
                    __syncthreads();
                    const float* hb = (c & 1) ? stg1 : stg0;
                    const int kg = c * 128 + w * 16;
#pragma unroll 4
                    for (int kk = 0; kk < 16; ++kk) {
                        float2 h2 = *(const float2*)(hb + (w * 16 + kk) * 64 + 2 * ln);
                        ull hx = dup2(h2.x), hy = dup2(h2.y);
                        const ulonglong2* wp = (const ulonglong2*)(wsq + (size_t)(kg + kk) * 8);
                        ulonglong2 u0 = wp[0], u1 = wp[1], u2 = wp[2], u3 = wp[3];
                        a0[0] = ffma2(hx, u0.x, a0[0]); a1[0] = ffma2(hy, u0.x, a1[0]);
                        a0[1] = ffma2(hx, u0.y, a0[1]); a1[1] = ffma2(hy, u0.y, a1[1]);
                        a0[2] = ffma2(hx, u1.x, a0[2]); a1[2] = ffma2(hy, u1.x, a1[2]);
                        a0[3] = ffma2(hx, u1.y, a0[3]); a1[3] = ffma2(hy, u1.y, a1[3]);
                        a0[4] = ffma2(hx, u2.x, a0[4]); a1[4] = ffma2(hy, u2.x, a1[4]);
                        a0[5] = ffma2(hx, u2.y, a0[5]); a1[5] = ffma2(hy, u2.y, a1[5]);
                        a0[6] = ffma2(hx, u3.x, a0[6]); a1[6] = ffma2(hy, u3.x, a1[6]);
                        a0[7] = ffma2(hx, u3.y, a0[7]); a1[7] = ffma2(hy, u3.y, a1[7]);
                    }
                    __syncthreads();
                }

                // two reduce passes of 8 cols each
#pragma unroll
                for (int p = 0; p < 2; ++p) {
#pragma unroll
                    for (int q = 0; q < 4; ++q) {
                        redq[(w * 64 + 2 * ln)     * 4 + q] = a0[p * 4 + q];
                        redq[(w * 64 + 2 * ln + 1) * 4 + q] = a1[p * 4 + q];
                    }
                    __syncthreads();
                    float s0 = bB0[p], s1 = bB1[p];
#pragma unroll
                    for (int ww = 0; ww < 8; ++ww) {
                        float2 t2 = *(const float2*)&red[(ww * 64 + rr) * 8 + jj];
                        s0 += t2.x; s1 += t2.y;
                    }
                    s0 = tanh_acc(s0);
                    s1 = tanh_acc(s1);
                    float* dst = g_h1T[r];
                    const int c = c0 + p * 8 + jj;
                    stcg(dst + (c)     * 64 + rr, s0);
                    stcg(dst + (c + 1) * 64 + rr, s1);
                    __syncthreads();
                }
            }
            if (r < TT - 1) {
                if (tid == 0) {
                    asm volatile("red.release.gpu.global.add.u32 [%0], 1;"
                                 :: "l"(&g_bar) : "memory");
                    const unsigned tgt = (unsigned)(r + 1) * 64u;
                    unsigned v;
                    do {
                        asm volatile("ld.acquire.gpu.global.u32 %0, [%1];"
                                     : "=r"(v) : "l"(&g_bar) : "memory");
                    } while (v < tgt);
                }
                __syncthreads();
            }
        }
    }
}

// ---------------- GEMM 1: out = tanh([o0_t | h1_{t-1}] @ Wo1 + bo1) --------
__global__ __launch_bounds__(256)
void gemm1(const float* __restrict__ Wo1, const float* __restrict__ bo1,
           float* __restrict__ out)
{
    __shared__ __align__(16) float2 As2[16][128];
    __shared__ __align__(16) float  Bs[16][128];

    const int tid = threadIdx.x;
    const int m0 = blockIdx.y * 128;
    const int n0 = blockIdx.x * 128;

    const int kk = tid >> 5;
    const int mm = (tid & 31) << 2;
    const int t  = (m0 >> 6) + (mm >> 6);
    const int b  = mm & 63;
    const size_t aoff = (size_t)t * (512 * 64) + b;

    const int bk = tid >> 5;
    const int bn = (tid & 31) << 2;

    const int ty = tid >> 4, tx = tid & 15;

    ull acc[8][4];
#pragma unroll
    for (int i = 0; i < 8; ++i)
#pragma unroll
        for (int j = 0; j < 4; ++j) acc[i][j] = 0ull;

    for (int k0 = 0; k0 < 1024; k0 += 16) {
        const float* Abase = (k0 < 512) ? &g_o0T[0][0] : &g_h1T[0][0];
        const int koff = (k0 < 512) ? k0 : (k0 - 512);
        float4 av0 = *(const float4*)(Abase + aoff + (size_t)(koff + kk) * 64);
        float4 av1 = *(const float4*)(Abase + aoff + (size_t)(koff + kk + 8) * 64);
        float4 bv0 = *(const float4*)(Wo1 + (size_t)(k0 + bk) * 512 + n0 + bn);
        float4 bv1 = *(const float4*)(Wo1 + (size_t)(k0 + bk + 8) * 512 + n0 + bn);
        __syncthreads();
        As2[kk][mm + 0] = make_float2(av0.x, av0.x);
        As2[kk][mm + 1] = make_float2(av0.y, av0.y);
        As2[kk][mm + 2] = make_float2(av0.z, av0.z);
        As2[kk][mm + 3] = make_float2(av0.w, av0.w);
        As2[kk + 8][mm + 0] = make_float2(av1.x, av1.x);
        As2[kk + 8][mm + 1] = make_float2(av1.y, av1.y);
        As2[kk + 8][mm + 2] = make_float2(av1.z, av1.z);
        As2[kk + 8][mm + 3] = make_float2(av1.w, av1.w);
        *(float4*)&Bs[bk][bn]     = bv0;
        *(float4*)&Bs[bk + 8][bn] = bv1;
        __syncthreads();
#pragma unroll
        for (int k = 0; k < 16; ++k) {
            ulonglong2 a01 = *(const ulonglong2*)&As2[k][ty * 8 + 0];
            ulonglong2 a23 = *(const ulonglong2*)&As2[k][ty * 8 + 2];
            ulonglong2 a45 = *(const ulonglong2*)&As2[k][ty * 8 + 4];
            ulonglong2 a67 = *(const ulonglong2*)&As2[k][ty * 8 + 6];
            ulonglong2 b03 = *(const ulonglong2*)&Bs[k][tx * 8 + 0];
            ulonglong2 b47 = *(const ulonglong2*)&Bs[k][tx * 8 + 4];
            ull a[8] = {a01.x, a01.y, a23.x, a23.y, a45.x, a45.y, a67.x, a67.y};
            ull b2[4] = {b03.x, b03.y, b47.x, b47.y};
#pragma unroll
            for (int i = 0; i < 8; ++i)
#pragma unroll
                for (int j = 0; j < 4; ++j)
                    acc[i][j] = ffma2(a[i], b2[j], acc[i][j]);
        }
    }

    float4 bia0 = *(const float4*)(bo1 + n0 + tx * 8);
    float4 bia1 = *(const float4*)(bo1 + n0 + tx * 8 + 4);
#pragma unroll
    for (int i = 0; i < 8; ++i) {
        const int m  = m0 + ty * 8 + i;
        const int tt = m >> 6, bb = m & 63;
        float* cp = out + ((size_t)bb * TT + tt) * 512 + n0 + tx * 8;
        float2 v0 = unpk(acc[i][0]);
        float2 v1 = unpk(acc[i][1]);
        float2 v2 = unpk(acc[i][2]);
        float2 v3 = unpk(acc[i][3]);
        float4 o0, o1;
        o0.x = tanh_acc(v0.x + bia0.x);
        o0.y = tanh_acc(v0.y + bia0.y);
        o0.z = tanh_acc(v1.x + bia0.z);
        o0.w = tanh_acc(v1.y + bia0.w);
        o1.x = tanh_acc(v2.x + bia1.x);
        o1.y = tanh_acc(v2.y + bia1.y);
        o1.z = tanh_acc(v3.x + bia1.z);
        o1.w = tanh_acc(v3.y + bia1.w);
        *(float4*)cp       = o0;
        *(float4*)(cp + 4) = o1;
    }
}

// ---------------- launch ---------------------------------------------------
extern "C" void kernel_launch(void* const* d_in, const int* in_sizes, int n_in,
                              void* d_out, int out_size)
{
    const float* x   = (const float*)d_in[0];
    const float* enc = (const float*)d_in[1];
    const float* Wh0 = (const float*)d_in[2];
    const float* bh0 = (const float*)d_in[3];
    const float* Wo0 = (const float*)d_in[4];
    const float* bo0 = (const float*)d_in[5];
    const float* Wh1 = (const float*)d_in[6];
    const float* bh1 = (const float*)d_in[7];
    const float* Wo1 = (const float*)d_in[8];
    const float* bo1 = (const float*)d_in[9];
    float* out = (float*)d_out;

    static int smem_set = 0;
    if (!smem_set) {
        cudaFuncSetAttribute(scan_fused,
                             cudaFuncAttributeMaxDynamicSharedMemorySize, 147456);
        smem_set = 1;
    }

    pack0<<<(DD * 1024 + 255) / 256, 256>>>(Wh0, Wo0, bh0, bo0);
    init_state<<<(HH * BB + 255) / 256, 256>>>(enc);
    gemm0<<<dim3(8, 128), 256>>>(x);
    scan_fused<<<64, 256, 147456>>>(Wh1, bh1);
    gemm1<<<dim3(4, 128), 256>>>(Wo1, bo1, out);
}

// round 14
// speedup vs baseline: 1.1845x; 1.1845x over previous
#include <cuda_runtime.h>

#define BB 64
#define TT 256
#define DD 512
#define HH 512

typedef unsigned long long ull;

// ---------------- scratch (static device allocations only) ----------------
__device__ __align__(16) float g_h0T[2][HH * BB];        // h0 [k][b], double buffered
__device__ __align__(16) float g_o0T[TT][DD * BB];       // o0_t [k][b] history
__device__ __align__(16) float g_h1T[TT][HH * BB];       // g_h1T[t] = h1_{t-1}
__device__ __align__(16) float g_P0[(size_t)TT * BB * 1024]; // x @ W0x
__device__ __align__(16) float g_W0x[DD * 1024];
__device__ __align__(16) float g_W0r[HH * 1024];
__device__ float g_b0[1024];
__device__ unsigned int g_bar;

// ---------------- helpers --------------------------------------------------
__device__ __forceinline__ ull ffma2(ull a, ull b, ull c) {
    ull d; asm("fma.rn.f32x2 %0, %1, %2, %3;" : "=l"(d) : "l"(a), "l"(b), "l"(c));
    return d;
}
__device__ __forceinline__ ull dup2(float x) {
    ull d; asm("mov.b64 %0, {%1, %1};" : "=l"(d) : "f"(x));
    return d;
}
__device__ __forceinline__ float2 unpk(ull a) {
    float2 v; asm("mov.b64 {%0, %1}, %2;" : "=f"(v.x), "=f"(v.y) : "l"(a));
    return v;
}
__device__ __forceinline__ float2 ldcg2(const float* p) {
    float2 v;
    asm volatile("ld.global.cg.v2.f32 {%0,%1}, [%2];" : "=f"(v.x), "=f"(v.y) : "l"(p));
    return v;
}
__device__ __forceinline__ void stcg(float* p, float v) {
    asm volatile("st.global.cg.f32 [%0], %1;" :: "l"(p), "f"(v));
}
__device__ __forceinline__ void cpasync16(unsigned saddr, const float* gptr) {
    asm volatile("cp.async.cg.shared.global [%0], [%1], 16;" :: "r"(saddr), "l"(gptr));
}
__device__ __forceinline__ void cp_commit() {
    asm volatile("cp.async.commit_group;");
}
template <int N>
__device__ __forceinline__ void cp_wait() {
    asm volatile("cp.async.wait_group %0;" :: "n"(N));
}
// Accurate tanh independent of --use_fast_math.
__device__ __forceinline__ float tanh_acc(float x) {
    float ax = fabsf(x);
    float u  = expm1f(-2.0f * ax);
    float r  = -u / (2.0f + u);
    return x >= 0.0f ? r : -r;
}

// ---------------- layer-0 weight packing ----------------------------------
__global__ void pack0(const float* __restrict__ Wh0, const float* __restrict__ Wo0,
                      const float* __restrict__ bh0, const float* __restrict__ bo0)
{
    int idx = blockIdx.x * blockDim.x + threadIdx.x;
    if (idx >= DD * 1024) return;
    int k = idx >> 10, n = idx & 1023;
    bool hc = n < HH;
    int c = hc ? n : n - HH;
    g_W0x[idx] = hc ? Wh0[k * HH + c]        : Wo0[k * DD + c];
    g_W0r[idx] = hc ? Wh0[(DD + k) * HH + c] : Wo0[(DD + k) * DD + c];
    if (idx < 1024) g_b0[idx] = hc ? bh0[c] : bo0[c];
}

__global__ void init_state(const float* __restrict__ enc) {
    int idx = blockIdx.x * blockDim.x + threadIdx.x;
    if (idx < HH * BB) {
        int k = idx >> 6, b = idx & 63;
        g_h0T[0][k * 64 + b] = enc[b * HH + k];
        g_h1T[0][idx] = 0.0f;
    }
    if (idx == 0) g_bar = 0u;
}

// ---------------- GEMM 0: P0[m,0:1024] = x_row(m) @ W0x,  m = t*64+b -------
__global__ __launch_bounds__(256)
void gemm0(const float* __restrict__ x)
{
    __shared__ __align__(16) float2 As2[16][128];
    __shared__ __align__(16) float  Bs[16][128];

    const int tid = threadIdx.x;
    const int m0 = blockIdx.y * 128;
    const int n0 = blockIdx.x * 128;

    const int ai = tid >> 2;
    const int ak = (tid & 3) << 2;
    const int mg0 = m0 + ai, mg1 = m0 + ai + 64;
    const float* ap0 = x + (size_t)(mg0 & 63) * (TT * DD) + (size_t)(mg0 >> 6) * DD + ak;
    const float* ap1 = x + (size_t)(mg1 & 63) * (TT * DD) + (size_t)(mg1 >> 6) * DD + ak;

    const int bk = tid >> 5;
    const int bn = (tid & 31) << 2;
    const float* bp = g_W0x + (size_t)bk * 1024 + n0 + bn;

    const int ty = tid >> 4, tx = tid & 15;

    ull acc[8][4];
#pragma unroll
    for (int i = 0; i < 8; ++i)
#pragma unroll
        for (int j = 0; j < 4; ++j) acc[i][j] = 0ull;

    for (int k0 = 0; k0 < DD; k0 += 16) {
        float4 av0 = *(const float4*)(ap0 + k0);
        float4 av1 = *(const float4*)(ap1 + k0);
        float4 bv0 = *(const float4*)(bp + (size_t)k0 * 1024);
        float4 bv1 = *(const float4*)(bp + (size_t)(k0 + 8) * 1024);
        __syncthreads();
        As2[ak + 0][ai] = make_float2(av0.x, av0.x);
        As2[ak + 1][ai] = make_float2(av0.y, av0.y);
        As2[ak + 2][ai] = make_float2(av0.z, av0.z);
        As2[ak + 3][ai] = make_float2(av0.w, av0.w);
        As2[ak + 0][ai + 64] = make_float2(av1.x, av1.x);
        As2[ak + 1][ai + 64] = make_float2(av1.y, av1.y);
        As2[ak + 2][ai + 64] = make_float2(av1.z, av1.z);
        As2[ak + 3][ai + 64] = make_float2(av1.w, av1.w);
        *(float4*)&Bs[bk][bn]     = bv0;
        *(float4*)&Bs[bk + 8][bn] = bv1;
        __syncthreads();
#pragma unroll
        for (int k = 0; k < 16; ++k) {
            ulonglong2 a01 = *(const ulonglong2*)&As2[k][ty * 8 + 0];
            ulonglong2 a23 = *(const ulonglong2*)&As2[k][ty * 8 + 2];
            ulonglong2 a45 = *(const ulonglong2*)&As2[k][ty * 8 + 4];
            ulonglong2 a67 = *(const ulonglong2*)&As2[k][ty * 8 + 6];
            ulonglong2 b03 = *(const ulonglong2*)&Bs[k][tx * 8 + 0];
            ulonglong2 b47 = *(const ulonglong2*)&Bs[k][tx * 8 + 4];
            ull a[8] = {a01.x, a01.y, a23.x, a23.y, a45.x, a45.y, a67.x, a67.y};
            ull b[4] = {b03.x, b03.y, b47.x, b47.y};
#pragma unroll
            for (int i = 0; i < 8; ++i)
#pragma unroll
                for (int j = 0; j < 4; ++j)
                    acc[i][j] = ffma2(a[i], b[j], acc[i][j]);
        }
    }
#pragma unroll
    for (int i = 0; i < 8; ++i) {
        float* cp = g_P0 + (size_t)(m0 + ty * 8 + i) * 1024 + n0 + tx * 8;
        *(ulonglong2*)cp       = make_ulonglong2(acc[i][0], acc[i][1]);
        *(ulonglong2*)(cp + 4) = make_ulonglong2(acc[i][2], acc[i][3]);
    }
}

// ---------------- fused scan: batch-split CTAs ------------------------------
// bx < 64  : "A" CTA — colgroup g=bx>>1 (32 packed cols), batch half bx&1, K=512
// bx >= 64 : "B" CTA — colgroup (bx-64)>>1 (16 h1 cols), batch half, K=1024
// Each CTA stages only its 32-row batch slice: chip traffic 12 MB/round.
// 3-buffer (16KB) cp.async ring, 2-ahead.
// SMEM floats: Ws 16384 | stg 12288 (3x4096) | red 8192 = 144 KB.
__global__ __launch_bounds__(256)
void scan_fused(const float* __restrict__ Wh1, const float* __restrict__ bh1)
{
    extern __shared__ __align__(16) float sm[];
    float* Ws  = sm;             // 16384 floats
    float* stg = sm + 16384;     // 12288 floats (3 x 4096)
    ull*  redq = (ull*)(sm + 28672); // 4096 ull (32 KB)

    const int tid = threadIdx.x;
    const int bx  = blockIdx.x;
    const int w   = tid >> 5, ln = tid & 31;
    const int cp  = tid >> 5;            // reduce colpair group (= warp id)
    const int rowR = tid & 31;           // reduce row (= lane)
    const ull* wsq = (const ull*)Ws;
    const unsigned sbase = (unsigned)__cvta_generic_to_shared(stg);

    if (bx < 64) {
        // ========== A: 32 packed cols of [h0|o0], K=512, 32 batch rows ======
        const int n0 = (bx >> 1) * 32;
        const int b0 = (bx & 1) * 32;

        for (int i = tid; i < 512 * 32; i += 256) {
            int k = i >> 5, j = i & 31;
            Ws[i] = g_W0r[k * 1024 + n0 + j];
        }
        const float bA0x = g_b0[n0 + 2 * cp];
        const float bA0y = g_b0[n0 + 2 * cp + 1];
        const float bA1x = g_b0[n0 + 2 * (cp + 8)];
        const float bA1y = g_b0[n0 + 2 * (cp + 8) + 1];
        __syncthreads();

        for (int r = 0; r < TT; ++r) {
            float2 pA = ldcg2(&g_P0[((size_t)r * 64 + b0 + rowR) * 1024 + n0 + 2 * cp]);
            float2 pB = ldcg2(&g_P0[((size_t)r * 64 + b0 + rowR) * 1024 + n0 + 2 * (cp + 8)]);
            const float* hsrc = g_h0T[r & 1];

            // stage chunks 0,1 into buffers 0,1 (16 KB = 1024 x 16B units each)
#pragma unroll
            for (int cc = 0; cc < 2; ++cc) {
#pragma unroll
                for (int i = 0; i < 4; ++i) {
                    int u = tid + i * 256;
                    cpasync16(sbase + (unsigned)(cc * 16384 + u * 16),
                              hsrc + (cc * 128 + (u >> 3)) * 64 + b0 + ((u & 7) << 2));
                }
                cp_commit();
            }

            ull acc[16];
#pragma unroll
            for (int q = 0; q < 16; ++q) acc[q] = 0ull;

#pragma unroll
            for (int c = 0; c < 4; ++c) {
                if (c + 2 < 4) {
                    const int cn = c + 2;
                    const unsigned dst = sbase + (unsigned)((cn % 3) * 16384);
#pragma unroll
                    for (int i = 0; i < 4; ++i) {
                        int u = tid + i * 256;
                        cpasync16(dst + (unsigned)(u * 16),
                                  hsrc + (cn * 128 + (u >> 3)) * 64 + b0 + ((u & 7) << 2));
                    }
                    cp_commit();
                    cp_wait<2>();
                } else if (c + 1 < 4) {
                    cp_wait<1>();
                } else {
                    cp_wait<0>();
                }
                __syncthreads();
                const float* hb = stg + (c % 3) * 4096;
#pragma unroll 2
                for (int kk = 0; kk < 16; ++kk) {
                    const int k = c * 128 + w * 16 + kk;
                    float h = hb[(w * 16 + kk) * 32 + ln];
                    ull hx = dup2(h);
                    const ulonglong2* wp = (const ulonglong2*)(wsq + (size_t)k * 16);
#pragma unroll
                    for (int j = 0; j < 8; ++j) {
                        ulonglong2 uw = wp[j];
                        acc[2 * j]     = ffma2(hx, uw.x, acc[2 * j]);
                        acc[2 * j + 1] = ffma2(hx, uw.y, acc[2 * j + 1]);
                    }
                }
                __syncthreads();
            }

            // reduce: conflict-free colpair-major layout
#pragma unroll
            for (int q = 0; q < 16; ++q)
                redq[(w * 32 + ln) + q * 256] = acc[q];
            __syncthreads();

            float s0 = pA.x + bA0x, s1 = pA.y + bA0y;
            float s2 = pB.x + bA1x, s3 = pB.y + bA1y;
#pragma unroll
            for (int ww = 0; ww < 8; ++ww) {
                float2 t0 = unpk(redq[(ww * 32 + rowR) + cp * 256]);
                float2 t1 = unpk(redq[(ww * 32 + rowR) + (cp + 8) * 256]);
                s0 += t0.x; s1 += t0.y;
                s2 += t1.x; s3 += t1.y;
            }
            s0 = tanh_acc(s0); s1 = tanh_acc(s1);
            s2 = tanh_acc(s2); s3 = tanh_acc(s3);

            const int ca = n0 + 2 * cp;
            const int cb = n0 + 2 * (cp + 8);
            const int rb = b0 + rowR;
            if (n0 < 512) {
                float* dst = g_h0T[(r + 1) & 1];
                stcg(dst + (ca)     * 64 + rb, s0);
                stcg(dst + (ca + 1) * 64 + rb, s1);
                stcg(dst + (cb)     * 64 + rb, s2);
                stcg(dst + (cb + 1) * 64 + rb, s3);
            } else {
                float* dst = g_o0T[r];
                stcg(dst + (ca - 512) * 64 + rb, s0);
                stcg(dst + (ca - 511) * 64 + rb, s1);
                stcg(dst + (cb - 512) * 64 + rb, s2);
                stcg(dst + (cb - 511) * 64 + rb, s3);
            }
            __syncthreads();

            if (r < TT - 1) {
                if (tid == 0) {
                    asm volatile("red.release.gpu.global.add.u32 [%0], 1;"
                                 :: "l"(&g_bar) : "memory");
                    const unsigned tgt = (unsigned)(r + 1) * 128u;
                    unsigned v;
                    do {
                        asm volatile("ld.acquire.gpu.global.u32 %0, [%1];"
                                     : "=r"(v) : "l"(&g_bar) : "memory");
                    } while (v < tgt);
                }
                __syncthreads();
            }
        }
    } else {
        // ========== B: 16 h1 cols, K=1024, 32 batch rows, one step behind ===
        const int uB = bx - 64;
        const int c0 = (uB >> 1) * 16;
        const int b0 = (uB & 1) * 32;

        for (int i = tid; i < 1024 * 16; i += 256) {
            int k = i >> 4, j = i & 15;
            Ws[i] = Wh1[k * 512 + c0 + j];
        }
        const float bBx = bh1[c0 + 2 * cp];
        const float bBy = bh1[c0 + 2 * cp + 1];
        __syncthreads();

        for (int r = 0; r < TT; ++r) {
            if (r >= 1) {
                const int t1 = r - 1;
                const float* srcA = g_o0T[t1];   // k in [0, 512)
                const float* srcH = g_h1T[t1];   // k in [512, 1024)

                // stage chunks 0,1 into buffers 0,1
#pragma unroll
                for (int cc = 0; cc < 2; ++cc) {
#pragma unroll
                    for (int i = 0; i < 4; ++i) {
                        int u = tid + i * 256;
                        cpasync16(sbase + (unsigned)(cc * 16384 + u * 16),
                                  srcA + (cc * 128 + (u >> 3)) * 64 + b0 + ((u & 7) << 2));
                    }
                    cp_commit();
                }

                ull acc[8];
#pragma unroll
                for (int q = 0; q < 8; ++q) acc[q] = 0ull;

#pragma unroll
                for (int c = 0; c < 8; ++c) {
                    if (c + 2 < 8) {
                        const int cn = c + 2;
                        const float* src = (cn < 4) ? (srcA + cn * 128 * 64)
                                                    : (srcH + (cn - 4) * 128 * 64);
                        const unsigned dst = sbase + (unsigned)((cn % 3) * 16384);
#pragma unroll
                        for (int i = 0; i < 4; ++i) {
                            int u = tid + i * 256;
                            cpasync16(dst + (unsigned)(u * 16),
                                      src + (u >> 3) * 64 + b0 + ((u & 7) << 2));
                        }
                        cp_commit();
                        cp_wait<2>();
                    } else if (c + 1 < 8) {
                        cp_wait<1>();
                    } else {
                        cp_wait<0>();
                    }
                    __syncthreads();
                    const float* hb = stg + (c % 3) * 4096;
#pragma unroll 4
                    for (int kk = 0; kk < 16; ++kk) {
                        const int k = c * 128 + w * 16 + kk;
                        float h = hb[(w * 16 + kk) * 32 + ln];
                        ull hx = dup2(h);
                        const ulonglong2* wp = (const ulonglong2*)(wsq + (size_t)k * 8);
                        ulonglong2 u0 = wp[0], u1 = wp[1], u2 = wp[2], u3 = wp[3];
                        acc[0] = ffma2(hx, u0.x, acc[0]);
                        acc[1] = ffma2(hx, u0.y, acc[1]);
                        acc[2] = ffma2(hx, u1.x, acc[2]);
                        acc[3] = ffma2(hx, u1.y, acc[3]);
                        acc[4] = ffma2(hx, u2.x, acc[4]);
                        acc[5] = ffma2(hx, u2.y, acc[5]);
                        acc[6] = ffma2(hx, u3.x, acc[6]);
                        acc[7] = ffma2(hx, u3.y, acc[7]);
                    }
                    __syncthreads();
                }

#pragma unroll
                for (int q = 0; q < 8; ++q)
                    redq[(w * 32 + ln) + q * 256] = acc[q];
                __syncthreads();

                float s0 = bBx, s1 = bBy;
#pragma unroll
                for (int ww = 0; ww < 8; ++ww) {
                    float2 t0 = unpk(redq[(ww * 32 + rowR) + cp * 256]);
                    s0 += t0.x; s1 += t0.y;
                }
                s0 = tanh_acc(s0);
                s1 = tanh_acc(s1);
                float* dst = g_h1T[r];
                const int rb = b0 + rowR;
                stcg(dst + (c0 + 2 * cp)     * 64 + rb, s0);
                stcg(dst + (c0 + 2 * cp + 1) * 64 + rb, s1);
                __syncthreads();
            }
            if (r < TT - 1) {
                if (tid == 0) {
                    asm volatile("red.release.gpu.global.add.u32 [%0], 1;"
                                 :: "l"(&g_bar) : "memory");
                    const unsigned tgt = (unsigned)(r + 1) * 128u;
                    unsigned v;
                    do {
                        asm volatile("ld.acquire.gpu.global.u32 %0, [%1];"
                                     : "=r"(v) : "l"(&g_bar) : "memory");
                    } while (v < tgt);
                }
                __syncthreads();
            }
        }
    }
}

// ---------------- GEMM 1: out = tanh([o0_t | h1_{t-1}] @ Wo1 + bo1) --------
__global__ __launch_bounds__(256)
void gemm1(const float* __restrict__ Wo1, const float* __restrict__ bo1,
           float* __restrict__ out)
{
    __shared__ __align__(16) float2 As2[16][128];
    __shared__ __align__(16) float  Bs[16][128];

    const int tid = threadIdx.x;
    const int m0 = blockIdx.y * 128;
    const int n0 = blockIdx.x * 128;

    const int kk = tid >> 5;
    const int mm = (tid & 31) << 2;
    const int t  = (m0 >> 6) + (mm >> 6);
    const int b  = mm & 63;
    const size_t aoff = (size_t)t * (512 * 64) + b;

    const int bk = tid >> 5;
    const int bn = (tid & 31) << 2;

    const int ty = tid >> 4, tx = tid & 15;

    ull acc[8][4];
#pragma unroll
    for (int i = 0; i < 8; ++i)
#pragma unroll
        for (int j = 0; j < 4; ++j) acc[i][j] = 0ull;

    for (int k0 = 0; k0 < 1024; k0 += 16) {
        const float* Abase = (k0 < 512) ? &g_o0T[0][0] : &g_h1T[0][0];
        const int koff = (k0 < 512) ? k0 : (k0 - 512);
        float4 av0 = *(const float4*)(Abase + aoff + (size_t)(koff + kk) * 64);
        float4 av1 = *(const float4*)(Abase + aoff + (size_t)(koff + kk + 8) * 64);
        float4 bv0 = *(const float4*)(Wo1 + (size_t)(k0 + bk) * 512 + n0 + bn);
        float4 bv1 = *(const float4*)(Wo1 + (size_t)(k0 + bk + 8) * 512 + n0 + bn);
        __syncthreads();
        As2[kk][mm + 0] = make_float2(av0.x, av0.x);
        As2[kk][mm + 1] = make_float2(av0.y, av0.y);
        As2[kk][mm + 2] = make_float2(av0.z, av0.z);
        As2[kk][mm + 3] = make_float2(av0.w, av0.w);
        As2[kk + 8][mm + 0] = make_float2(av1.x, av1.x);
        As2[kk + 8][mm + 1] = make_float2(av1.y, av1.y);
        As2[kk + 8][mm + 2] = make_float2(av1.z, av1.z);
        As2[kk + 8][mm + 3] = make_float2(av1.w, av1.w);
        *(float4*)&Bs[bk][bn]     = bv0;
        *(float4*)&Bs[bk + 8][bn] = bv1;
        __syncthreads();
#pragma unroll
        for (int k = 0; k < 16; ++k) {
            ulonglong2 a01 = *(const ulonglong2*)&As2[k][ty * 8 + 0];
            ulonglong2 a23 = *(const ulonglong2*)&As2[k][ty * 8 + 2];
            ulonglong2 a45 = *(const ulonglong2*)&As2[k][ty * 8 + 4];
            ulonglong2 a67 = *(const ulonglong2*)&As2[k][ty * 8 + 6];
            ulonglong2 b03 = *(const ulonglong2*)&Bs[k][tx * 8 + 0];
            ulonglong2 b47 = *(const ulonglong2*)&Bs[k][tx * 8 + 4];
            ull a[8] = {a01.x, a01.y, a23.x, a23.y, a45.x, a45.y, a67.x, a67.y};
            ull b2[4] = {b03.x, b03.y, b47.x, b47.y};
#pragma unroll
            for (int i = 0; i < 8; ++i)
#pragma unroll
                for (int j = 0; j < 4; ++j)
                    acc[i][j] = ffma2(a[i], b2[j], acc[i][j]);
        }
    }

    float4 bia0 = *(const float4*)(bo1 + n0 + tx * 8);
    float4 bia1 = *(const float4*)(bo1 + n0 + tx * 8 + 4);
#pragma unroll
    for (int i = 0; i < 8; ++i) {
        const int m  = m0 + ty * 8 + i;
        const int tt = m >> 6, bb = m & 63;
        float* cp = out + ((size_t)bb * TT + tt) * 512 + n0 + tx * 8;
        float2 v0 = unpk(acc[i][0]);
        float2 v1 = unpk(acc[i][1]);
        float2 v2 = unpk(acc[i][2]);
        float2 v3 = unpk(acc[i][3]);
        float4 o0, o1;
        o0.x = tanh_acc(v0.x + bia0.x);
        o0.y = tanh_acc(v0.y + bia0.y);
        o0.z = tanh_acc(v1.x + bia0.z);
        o0.w = tanh_acc(v1.y + bia0.w);
        o1.x = tanh_acc(v2.x + bia1.x);
        o1.y = tanh_acc(v2.y + bia1.y);
        o1.z = tanh_acc(v3.x + bia1.z);
        o1.w = tanh_acc(v3.y + bia1.w);
        *(float4*)cp       = o0;
        *(float4*)(cp + 4) = o1;
    }
}

// ---------------- launch ---------------------------------------------------
extern "C" void kernel_launch(void* const* d_in, const int* in_sizes, int n_in,
                              void* d_out, int out_size)
{
    const float* x   = (const float*)d_in[0];
    const float* enc = (const float*)d_in[1];
    const float* Wh0 = (const float*)d_in[2];
    const float* bh0 = (const float*)d_in[3];
    const float* Wo0 = (const float*)d_in[4];
    const float* bo0 = (const float*)d_in[5];
    const float* Wh1 = (const float*)d_in[6];
    const float* bh1 = (const float*)d_in[7];
    const float* Wo1 = (const float*)d_in[8];
    const float* bo1 = (const float*)d_in[9];
    float* out = (float*)d_out;

    static int smem_set = 0;
    if (!smem_set) {
        cudaFuncSetAttribute(scan_fused,
                             cudaFuncAttributeMaxDynamicSharedMemorySize, 147456);
        smem_set = 1;
    }

    pack0<<<(DD * 1024 + 255) / 256, 256>>>(Wh0, Wo0, bh0, bo0);
    init_state<<<(HH * BB + 255) / 256, 256>>>(enc);
    gemm0<<<dim3(8, 128), 256>>>(x);
    scan_fused<<<128, 256, 147456>>>(Wh1, bh1);
    gemm1<<<dim3(4, 128), 256>>>(Wo1, bo1, out);
}

// round 15
// speedup vs baseline: 1.3896x; 1.1731x over previous
#include <cuda_runtime.h>

#define BB 64
#define TT 256
#define DD 512
#define HH 512

typedef unsigned long long ull;

// ---------------- scratch (static device allocations only) ----------------
__device__ __align__(16) float g_h0T[2][HH * BB];        // h0 [k][b], double buffered
__device__ __align__(16) float g_o0T[TT][DD * BB];       // o0_t [k][b] history
__device__ __align__(16) float g_h1T[TT][HH * BB];       // g_h1T[t] = h1_{t-1}
__device__ __align__(16) float g_P0[(size_t)TT * BB * 1024]; // x @ W0x
__device__ __align__(16) float g_W0x[DD * 1024];
__device__ __align__(16) float g_W0r[HH * 1024];
__device__ float g_b0[1024];
__device__ unsigned int g_bar;

// ---------------- helpers --------------------------------------------------
__device__ __forceinline__ ull ffma2(ull a, ull b, ull c) {
    ull d; asm("fma.rn.f32x2 %0, %1, %2, %3;" : "=l"(d) : "l"(a), "l"(b), "l"(c));
    return d;
}
__device__ __forceinline__ ull dup2(float x) {
    ull d; asm("mov.b64 %0, {%1, %1};" : "=l"(d) : "f"(x));
    return d;
}
__device__ __forceinline__ float2 unpk(ull a) {
    float2 v; asm("mov.b64 {%0, %1}, %2;" : "=f"(v.x), "=f"(v.y) : "l"(a));
    return v;
}
__device__ __forceinline__ float2 ldcg2(const float* p) {
    float2 v;
    asm volatile("ld.global.cg.v2.f32 {%0,%1}, [%2];" : "=f"(v.x), "=f"(v.y) : "l"(p));
    return v;
}
__device__ __forceinline__ void stcg(float* p, float v) {
    asm volatile("st.global.cg.f32 [%0], %1;" :: "l"(p), "f"(v));
}
__device__ __forceinline__ void cpasync16(unsigned saddr, const float* gptr) {
    asm volatile("cp.async.cg.shared.global [%0], [%1], 16;" :: "r"(saddr), "l"(gptr));
}
__device__ __forceinline__ void cp_commit() {
    asm volatile("cp.async.commit_group;");
}
template <int N>
__device__ __forceinline__ void cp_wait() {
    asm volatile("cp.async.wait_group %0;" :: "n"(N));
}
// Accurate tanh independent of --use_fast_math.
__device__ __forceinline__ float tanh_acc(float x) {
    float ax = fabsf(x);
    float u  = expm1f(-2.0f * ax);
    float r  = -u / (2.0f + u);
    return x >= 0.0f ? r : -r;
}

// ---------------- layer-0 weight packing ----------------------------------
__global__ void pack0(const float* __restrict__ Wh0, const float* __restrict__ Wo0,
                      const float* __restrict__ bh0, const float* __restrict__ bo0)
{
    int idx = blockIdx.x * blockDim.x + threadIdx.x;
    if (idx >= DD * 1024) return;
    int k = idx >> 10, n = idx & 1023;
    bool hc = n < HH;
    int c = hc ? n : n - HH;
    g_W0x[idx] = hc ? Wh0[k * HH + c]        : Wo0[k * DD + c];
    g_W0r[idx] = hc ? Wh0[(DD + k) * HH + c] : Wo0[(DD + k) * DD + c];
    if (idx < 1024) g_b0[idx] = hc ? bh0[c] : bo0[c];
}

__global__ void init_state(const float* __restrict__ enc) {
    int idx = blockIdx.x * blockDim.x + threadIdx.x;
    if (idx < HH * BB) {
        int k = idx >> 6, b = idx & 63;
        g_h0T[0][k * 64 + b] = enc[b * HH + k];
        g_h1T[0][idx] = 0.0f;
    }
    if (idx == 0) g_bar = 0u;
}

// ---------------- GEMM 0: P0[m,0:1024] = x_row(m) @ W0x,  m = t*64+b -------
__global__ __launch_bounds__(256)
void gemm0(const float* __restrict__ x)
{
    __shared__ __align__(16) float2 As2[16][128];
    __shared__ __align__(16) float  Bs[16][128];

    const int tid = threadIdx.x;
    const int m0 = blockIdx.y * 128;
    const int n0 = blockIdx.x * 128;

    const int ai = tid >> 2;
    const int ak = (tid & 3) << 2;
    const int mg0 = m0 + ai, mg1 = m0 + ai + 64;
    const float* ap0 = x + (size_t)(mg0 & 63) * (TT * DD) + (size_t)(mg0 >> 6) * DD + ak;
    const float* ap1 = x + (size_t)(mg1 & 63) * (TT * DD) + (size_t)(mg1 >> 6) * DD + ak;

    const int bk = tid >> 5;
    const int bn = (tid & 31) << 2;
    const float* bp = g_W0x + (size_t)bk * 1024 + n0 + bn;

    const int ty = tid >> 4, tx = tid & 15;

    ull acc[8][4];
#pragma unroll
    for (int i = 0; i < 8; ++i)
#pragma unroll
        for (int j = 0; j < 4; ++j) acc[i][j] = 0ull;

    for (int k0 = 0; k0 < DD; k0 += 16) {
        float4 av0 = *(const float4*)(ap0 + k0);
        float4 av1 = *(const float4*)(ap1 + k0);
        float4 bv0 = *(const float4*)(bp + (size_t)k0 * 1024);
        float4 bv1 = *(const float4*)(bp + (size_t)(k0 + 8) * 1024);
        __syncthreads();
        As2[ak + 0][ai] = make_float2(av0.x, av0.x);
        As2[ak + 1][ai] = make_float2(av0.y, av0.y);
        As2[ak + 2][ai] = make_float2(av0.z, av0.z);
        As2[ak + 3][ai] = make_float2(av0.w, av0.w);
        As2[ak + 0][ai + 64] = make_float2(av1.x, av1.x);
        As2[ak + 1][ai + 64] = make_float2(av1.y, av1.y);
        As2[ak + 2][ai + 64] = make_float2(av1.z, av1.z);
        As2[ak + 3][ai + 64] = make_float2(av1.w, av1.w);
        *(float4*)&Bs[bk][bn]     = bv0;
        *(float4*)&Bs[bk + 8][bn] = bv1;
        __syncthreads();
#pragma unroll
        for (int k = 0; k < 16; ++k) {
            ulonglong2 a01 = *(const ulonglong2*)&As2[k][ty * 8 + 0];
            ulonglong2 a23 = *(const ulonglong2*)&As2[k][ty * 8 + 2];
            ulonglong2 a45 = *(const ulonglong2*)&As2[k][ty * 8 + 4];
            ulonglong2 a67 = *(const ulonglong2*)&As2[k][ty * 8 + 6];
            ulonglong2 b03 = *(const ulonglong2*)&Bs[k][tx * 8 + 0];
            ulonglong2 b47 = *(const ulonglong2*)&Bs[k][tx * 8 + 4];
            ull a[8] = {a01.x, a01.y, a23.x, a23.y, a45.x, a45.y, a67.x, a67.y};
            ull b[4] = {b03.x, b03.y, b47.x, b47.y};
#pragma unroll
            for (int i = 0; i < 8; ++i)
#pragma unroll
                for (int j = 0; j < 4; ++j)
                    acc[i][j] = ffma2(a[i], b[j], acc[i][j]);
        }
    }
#pragma unroll
    for (int i = 0; i < 8; ++i) {
        float* cp = g_P0 + (size_t)(m0 + ty * 8 + i) * 1024 + n0 + tx * 8;
        *(ulonglong2*)cp       = make_ulonglong2(acc[i][0], acc[i][1]);
        *(ulonglong2*)(cp + 4) = make_ulonglong2(acc[i][2], acc[i][3]);
    }
}

// ---------------- fused pipelined scan (champion + conflict-free reduce) ----
// bx < 64  : "A" CTA — 16 cols of [h0|o0], K=512 vs g_h0T
// bx >= 64 : "B" CTA — 8 cols of h1, K=1024 vs [o0_{t-1} | h1_{t-2}]
// Staging identical to the 2656us champion. ONLY the reduce changed:
// layout redq[(w*NC + c)*66 + row] with paired ulonglong2 stores ->
// conflict-free STS.128 (was 16-way conflicted), single pass on A side.
// SMEM floats: Ws 8192 | stg0 16384 | stg1 16384 | red 8448 = 197632 B.
__global__ __launch_bounds__(256)
void scan_fused(const float* __restrict__ Wh1, const float* __restrict__ bh1)
{
    extern __shared__ __align__(16) float sm[];
    float* Ws   = sm;            // 8192 floats
    float* stg0 = sm + 8192;     // 16384 floats
    float* stg1 = sm + 24576;    // 16384 floats
    ull*  redq  = (ull*)(sm + 40960); // 4224 ull = 33 KB

    const int tid = threadIdx.x;
    const int bx  = blockIdx.x;
    const int w   = tid >> 5, ln = tid & 31;
    const int rr  = tid >> 2;
    const int jj  = (tid & 3) << 1;
    const ull* wsq = (const ull*)Ws;

    const unsigned s0addr = (unsigned)__cvta_generic_to_shared(stg0);
    const unsigned s1addr = (unsigned)__cvta_generic_to_shared(stg1);

    if (bx < 64) {
        // ================= A: layer-0 recurrent part =================
        const int n0 = bx * 16;
        for (int i = tid; i < 512 * 16; i += 256) {
            int k = i >> 4, j = i & 15;
            Ws[i] = g_W0r[k * 1024 + n0 + j];
        }
        float bA00 = g_b0[n0 + jj],     bA01 = g_b0[n0 + jj + 1];
        float bA10 = g_b0[n0 + 8 + jj], bA11 = g_b0[n0 + 8 + jj + 1];
        const int cA = jj >> 1;          // colpair 0..3
        const int cB = cA + 4;           // colpair 4..7
        __syncthreads();

        for (int r = 0; r < TT; ++r) {
            float2 p0 = ldcg2(&g_P0[((size_t)r * 64 + rr) * 1024 + n0 + jj]);
            float2 p1 = ldcg2(&g_P0[((size_t)r * 64 + rr) * 1024 + n0 + 8 + jj]);
            const float* hsrc = g_h0T[r & 1];

            // stage chunk 0 (128 k rows = 32 KB = 2048 float4, 8 per thread)
#pragma unroll
            for (int i = 0; i < 8; ++i)
                cpasync16(s0addr + (tid + i * 256) * 16, hsrc + (tid + i * 256) * 4);
            cp_commit();

            ull a0[8], a1[8];
#pragma unroll
            for (int q = 0; q < 8; ++q) { a0[q] = 0ull; a1[q] = 0ull; }

#pragma unroll
            for (int c = 0; c < 4; ++c) {
                if (c < 3) {
                    const unsigned dst = (c & 1) ? s0addr : s1addr;
                    const float* src = hsrc + (c + 1) * 8192;
#pragma unroll
                    for (int i = 0; i < 8; ++i)
                        cpasync16(dst + (tid + i * 256) * 16, src + (tid + i * 256) * 4);
                    cp_commit();
                    cp_wait<1>();
                } else {
                    cp_wait<0>();
                }
                __syncthreads();
                const float* hb = (c & 1) ? stg1 : stg0;
                const int kg = c * 128 + w * 16;
#pragma unroll 4
                for (int kk = 0; kk < 16; ++kk) {
                    float2 h2 = *(const float2*)(hb + (w * 16 + kk) * 64 + 2 * ln);
                    ull hx = dup2(h2.x), hy = dup2(h2.y);
                    const ulonglong2* wp = (const ulonglong2*)(wsq + (size_t)(kg + kk) * 8);
                    ulonglong2 u0 = wp[0], u1 = wp[1], u2 = wp[2], u3 = wp[3];
                    a0[0] = ffma2(hx, u0.x, a0[0]); a1[0] = ffma2(hy, u0.x, a1[0]);
                    a0[1] = ffma2(hx, u0.y, a0[1]); a1[1] = ffma2(hy, u0.y, a1[1]);
                    a0[2] = ffma2(hx, u1.x, a0[2]); a1[2] = ffma2(hy, u1.x, a1[2]);
                    a0[3] = ffma2(hx, u1.y, a0[3]); a1[3] = ffma2(hy, u1.y, a1[3]);
                    a0[4] = ffma2(hx, u2.x, a0[4]); a1[4] = ffma2(hy, u2.x, a1[4]);
                    a0[5] = ffma2(hx, u2.y, a0[5]); a1[5] = ffma2(hy, u2.y, a1[5]);
                    a0[6] = ffma2(hx, u3.x, a0[6]); a1[6] = ffma2(hy, u3.x, a1[6]);
                    a0[7] = ffma2(hx, u3.y, a0[7]); a1[7] = ffma2(hy, u3.y, a1[7]);
                }
                __syncthreads();
            }

            // single-pass conflict-free reduce:
            // redq[(w*8+c)*66 + row] = packed (col 2c, col 2c+1) partial
#pragma unroll
            for (int c = 0; c < 8; ++c)
                *(ulonglong2*)&redq[(w * 8 + c) * 66 + 2 * ln] =
                    make_ulonglong2(a0[c], a1[c]);
            __syncthreads();

            float s0 = p0.x + bA00, s1 = p0.y + bA01;
            float s2 = p1.x + bA10, s3 = p1.y + bA11;
#pragma unroll
            for (int ww = 0; ww < 8; ++ww) {
                float2 t0 = unpk(redq[(ww * 8 + cA) * 66 + rr]);
                float2 t1 = unpk(redq[(ww * 8 + cB) * 66 + rr]);
                s0 += t0.x; s1 += t0.y;
                s2 += t1.x; s3 += t1.y;
            }
            s0 = tanh_acc(s0); s1 = tanh_acc(s1);
            s2 = tanh_acc(s2); s3 = tanh_acc(s3);

            const int ca = n0 + jj, cb = n0 + 8 + jj;
            if (n0 < 512) {
                float* dst = g_h0T[(r + 1) & 1];
                stcg(dst + (ca)     * 64 + rr, s0);
                stcg(dst + (ca + 1) * 64 + rr, s1);
                stcg(dst + (cb)     * 64 + rr, s2);
                stcg(dst + (cb + 1) * 64 + rr, s3);
            } else {
                float* dst = g_o0T[r];
                stcg(dst + (ca - 512) * 64 + rr, s0);
                stcg(dst + (ca - 511) * 64 + rr, s1);
                stcg(dst + (cb - 512) * 64 + rr, s2);
                stcg(dst + (cb - 511) * 64 + rr, s3);
            }
            __syncthreads();

            if (r < TT - 1) {
                if (tid == 0) {
                    asm volatile("red.release.gpu.global.add.u32 [%0], 1;"
                                 :: "l"(&g_bar) : "memory");
                    const unsigned tgt = (unsigned)(r + 1) * 128u;
                    unsigned v;
                    do {
                        asm volatile("ld.acquire.gpu.global.u32 %0, [%1];"
                                     : "=r"(v) : "l"(&g_bar) : "memory");
                    } while (v < tgt);
                }
                __syncthreads();
            }
        }
    } else {
        // ================= B: layer-1 hidden chain (one step behind) =========
        const int c0 = (bx - 64) * 8;
        for (int i = tid; i < 1024 * 8; i += 256) {
            int k = i >> 3, j = i & 7;
            Ws[i] = Wh1[k * 512 + c0 + j];
        }
        const float b0v = bh1[c0 + jj], b1v = bh1[c0 + jj + 1];
        const int cR = jj >> 1;          // colpair 0..3
        __syncthreads();

        for (int r = 0; r < TT; ++r) {
            if (r >= 1) {
                const int t1 = r - 1;
                const float* srcs[4] = {
                    g_o0T[t1], g_o0T[t1] + 16384,
                    g_h1T[t1], g_h1T[t1] + 16384
                };
#pragma unroll
                for (int i = 0; i < 16; ++i)
                    cpasync16(s0addr + (unsigned)((tid + i * 256) * 16),
                              srcs[0] + (tid + i * 256) * 4);
                cp_commit();

                ull a0[4], a1[4];
#pragma unroll
                for (int q = 0; q < 4; ++q) { a0[q] = 0ull; a1[q] = 0ull; }

#pragma unroll
                for (int c = 0; c < 4; ++c) {
                    if (c < 3) {
                        const unsigned dst = (c & 1) ? s0addr : s1addr;
                        const float* src = srcs[c + 1];
#pragma unroll
                        for (int i = 0; i < 16; ++i)
                            cpasync16(dst + (unsigned)((tid + i * 256) * 16),
                                      src + (tid + i * 256) * 4);
                        cp_commit();
                        cp_wait<1>();
                    } else {
                        cp_wait<0>();
                    }
                    __syncthreads();
                    const float* hb = (c & 1) ? stg1 : stg0;
                    const int kg = c * 256 + w * 32;
#pragma unroll 4
                    for (int q = 0; q < 32; ++q) {
                        float2 h2 = *(const float2*)(hb + (w * 32 + q) * 64 + 2 * ln);
                        ull hx = dup2(h2.x), hy = dup2(h2.y);
                        const ulonglong2* wp = (const ulonglong2*)(wsq + (size_t)(kg + q) * 4);
                        ulonglong2 u0 = wp[0], u1 = wp[1];
                        a0[0] = ffma2(hx, u0.x, a0[0]); a1[0] = ffma2(hy, u0.x, a1[0]);
                        a0[1] = ffma2(hx, u0.y, a0[1]); a1[1] = ffma2(hy, u0.y, a1[1]);
                        a0[2] = ffma2(hx, u1.x, a0[2]); a1[2] = ffma2(hy, u1.x, a1[2]);
                        a0[3] = ffma2(hx, u1.y, a0[3]); a1[3] = ffma2(hy, u1.y, a1[3]);
                    }
                    __syncthreads();
                }
                // conflict-free reduce store
#pragma unroll
                for (int q = 0; q < 4; ++q)
                    *(ulonglong2*)&redq[(w * 4 + q) * 66 + 2 * ln] =
                        make_ulonglong2(a0[q], a1[q]);
                __syncthreads();
                float s0 = b0v, s1 = b1v;
#pragma unroll
                for (int ww = 0; ww < 8; ++ww) {
                    float2 t2 = unpk(redq[(ww * 4 + cR) * 66 + rr]);
                    s0 += t2.x; s1 += t2.y;
                }
                s0 = tanh_acc(s0);
                s1 = tanh_acc(s1);
                float* dst = g_h1T[r];
                stcg(dst + (c0 + jj)     * 64 + rr, s0);
                stcg(dst + (c0 + jj + 1) * 64 + rr, s1);
                __syncthreads();
            }
            if (r < TT - 1) {
                if (tid == 0) {
                    asm volatile("red.release.gpu.global.add.u32 [%0], 1;"
                                 :: "l"(&g_bar) : "memory");
                    const unsigned tgt = (unsigned)(r + 1) * 128u;
                    unsigned v;
                    do {
                        asm volatile("ld.acquire.gpu.global.u32 %0, [%1];"
                                     : "=r"(v) : "l"(&g_bar) : "memory");
                    } while (v < tgt);
                }
                __syncthreads();
            }
        }
    }
}

// ---------------- GEMM 1: out = tanh([o0_t | h1_{t-1}] @ Wo1 + bo1) --------
__global__ __launch_bounds__(256)
void gemm1(const float* __restrict__ Wo1, const float* __restrict__ bo1,
           float* __restrict__ out)
{
    __shared__ __align__(16) float2 As2[16][128];
    __shared__ __align__(16) float  Bs[16][128];

    const int tid = threadIdx.x;
    const int m0 = blockIdx.y * 128;
    const int n0 = blockIdx.x * 128;

    const int kk = tid >> 5;
    const int mm = (tid & 31) << 2;
    const int t  = (m0 >> 6) + (mm >> 6);
    const int b  = mm & 63;
    const size_t aoff = (size_t)t * (512 * 64) + b;

    const int bk = tid >> 5;
    const int bn = (tid & 31) << 2;

    const int ty = tid >> 4, tx = tid & 15;

    ull acc[8][4];
#pragma unroll
    for (int i = 0; i < 8; ++i)
#pragma unroll
        for (int j = 0; j < 4; ++j) acc[i][j] = 0ull;

    for (int k0 = 0; k0 < 1024; k0 += 16) {
        const float* Abase = (k0 < 512) ? &g_o0T[0][0] : &g_h1T[0][0];
        const int koff = (k0 < 512) ? k0 : (k0 - 512);
        float4 av0 = *(const float4*)(Abase + aoff + (size_t)(koff + kk) * 64);
        float4 av1 = *(const float4*)(Abase + aoff + (size_t)(koff + kk + 8) * 64);
        float4 bv0 = *(const float4*)(Wo1 + (size_t)(k0 + bk) * 512 + n0 + bn);
        float4 bv1 = *(const float4*)(Wo1 + (size_t)(k0 + bk + 8) * 512 + n0 + bn);
        __syncthreads();
        As2[kk][mm + 0] = make_float2(av0.x, av0.x);
        As2[kk][mm + 1] = make_float2(av0.y, av0.y);
        As2[kk][mm + 2] = make_float2(av0.z, av0.z);
        As2[kk][mm + 3] = make_float2(av0.w, av0.w);
        As2[kk + 8][mm + 0] = make_float2(av1.x, av1.x);
        As2[kk + 8][mm + 1] = make_float2(av1.y, av1.y);
        As2[kk + 8][mm + 2] = make_float2(av1.z, av1.z);
        As2[kk + 8][mm + 3] = make_float2(av1.w, av1.w);
        *(float4*)&Bs[bk][bn]     = bv0;
        *(float4*)&Bs[bk + 8][bn] = bv1;
        __syncthreads();
#pragma unroll
        for (int k = 0; k < 16; ++k) {
            ulonglong2 a01 = *(const ulonglong2*)&As2[k][ty * 8 + 0];
            ulonglong2 a23 = *(const ulonglong2*)&As2[k][ty * 8 + 2];
            ulonglong2 a45 = *(const ulonglong2*)&As2[k][ty * 8 + 4];
            ulonglong2 a67 = *(const ulonglong2*)&As2[k][ty * 8 + 6];
            ulonglong2 b03 = *(const ulonglong2*)&Bs[k][tx * 8 + 0];
            ulonglong2 b47 = *(const ulonglong2*)&Bs[k][tx * 8 + 4];
            ull a[8] = {a01.x, a01.y, a23.x, a23.y, a45.x, a45.y, a67.x, a67.y};
            ull b2[4] = {b03.x, b03.y, b47.x, b47.y};
#pragma unroll
            for (int i = 0; i < 8; ++i)
#pragma unroll
                for (int j = 0; j < 4; ++j)
                    acc[i][j] = ffma2(a[i], b2[j], acc[i][j]);
        }
    }

    float4 bia0 = *(const float4*)(bo1 + n0 + tx * 8);
    float4 bia1 = *(const float4*)(bo1 + n0 + tx * 8 + 4);
#pragma unroll
    for (int i = 0; i < 8; ++i) {
        const int m  = m0 + ty * 8 + i;
        const int tt = m >> 6, bb = m & 63;
        float* cp = out + ((size_t)bb * TT + tt) * 512 + n0 + tx * 8;
        float2 v0 = unpk(acc[i][0]);
        float2 v1 = unpk(acc[i][1]);
        float2 v2 = unpk(acc[i][2]);
        float2 v3 = unpk(acc[i][3]);
        float4 o0, o1;
        o0.x = tanh_acc(v0.x + bia0.x);
        o0.y = tanh_acc(v0.y + bia0.y);
        o0.z = tanh_acc(v1.x + bia0.z);
        o0.w = tanh_acc(v1.y + bia0.w);
        o1.x = tanh_acc(v2.x + bia1.x);
        o1.y = tanh_acc(v2.y + bia1.y);
        o1.z = tanh_acc(v3.x + bia1.z);
        o1.w = tanh_acc(v3.y + bia1.w);
        *(float4*)cp       = o0;
        *(float4*)(cp + 4) = o1;
    }
}

// ---------------- launch ---------------------------------------------------
extern "C" void kernel_launch(void* const* d_in, const int* in_sizes, int n_in,
                              void* d_out, int out_size)
{
    const float* x   = (const float*)d_in[0];
    const float* enc = (const float*)d_in[1];
    const float* Wh0 = (const float*)d_in[2];
    const float* bh0 = (const float*)d_in[3];
    const float* Wo0 = (const float*)d_in[4];
    const float* bo0 = (const float*)d_in[5];
    const float* Wh1 = (const float*)d_in[6];
    const float* bh1 = (const float*)d_in[7];
    const float* Wo1 = (const float*)d_in[8];
    const float* bo1 = (const float*)d_in[9];
    float* out = (float*)d_out;

    static int smem_set = 0;
    if (!smem_set) {
        cudaFuncSetAttribute(scan_fused,
                             cudaFuncAttributeMaxDynamicSharedMemorySize, 197632);
        smem_set = 1;
    }

    pack0<<<(DD * 1024 + 255) / 256, 256>>>(Wh0, Wo0, bh0, bo0);
    init_state<<<(HH * BB + 255) / 256, 256>>>(enc);
    gemm0<<<dim3(8, 128), 256>>>(x);
    scan_fused<<<128, 256, 197632>>>(Wh1, bh1);
    gemm1<<<dim3(4, 128), 256>>>(Wo1, bo1, out);
}

// round 17
// speedup vs baseline: 1.7943x; 1.2913x over previous
#include <cuda_runtime.h>
#include <cuda_bf16.h>
#include <cstdint>

#define BB 64
#define TT 256
#define DD 512
#define HH 512

typedef unsigned long long ull;

// ---------------- scratch (static device allocations only) ----------------
__device__ __align__(16) float g_h0T[2][HH * BB];        // h0 [k][b], double buffered
__device__ __align__(16) float g_o0T[TT][DD * BB];       // o0_t [k][b] history
__device__ __align__(16) float g_h1T[TT][HH * BB];       // g_h1T[t] = h1_{t-1}
__device__ __align__(16) float g_P0[(size_t)TT * BB * 1024]; // x @ W0x
__device__ __align__(16) float g_W0r[HH * 1024];
__device__ float g_b0[1024];
__device__ unsigned int g_bar;

// bf16 split-precision operand copies for tensor-core GEMMs
__device__ __align__(16) __nv_bfloat16 g_xh[(size_t)16384 * 512];
__device__ __align__(16) __nv_bfloat16 g_xl[(size_t)16384 * 512];
__device__ __align__(16) __nv_bfloat16 g_w0h[1024 * 512];   // W0x^T [n][k]
__device__ __align__(16) __nv_bfloat16 g_w0l[1024 * 512];
__device__ __align__(16) __nv_bfloat16 g_a1h[(size_t)16384 * 1024];
__device__ __align__(16) __nv_bfloat16 g_a1l[(size_t)16384 * 1024];
__device__ __align__(16) __nv_bfloat16 g_w1h[512 * 1024];   // Wo1^T [n][k]
__device__ __align__(16) __nv_bfloat16 g_w1l[512 * 1024];

// ---------------- generic helpers ------------------------------------------
__device__ __forceinline__ ull ffma2(ull a, ull b, ull c) {
    ull d; asm("fma.rn.f32x2 %0, %1, %2, %3;" : "=l"(d) : "l"(a), "l"(b), "l"(c));
    return d;
}
__device__ __forceinline__ ull dup2(float x) {
    ull d; asm("mov.b64 %0, {%1, %1};" : "=l"(d) : "f"(x));
    return d;
}
__device__ __forceinline__ float2 unpk(ull a) {
    float2 v; asm("mov.b64 {%0, %1}, %2;" : "=f"(v.x), "=f"(v.y) : "l"(a));
    return v;
}
__device__ __forceinline__ float2 ldcg2(const float* p) {
    float2 v;
    asm volatile("ld.global.cg.v2.f32 {%0,%1}, [%2];" : "=f"(v.x), "=f"(v.y) : "l"(p));
    return v;
}
__device__ __forceinline__ void stcg(float* p, float v) {
    asm volatile("st.global.cg.f32 [%0], %1;" :: "l"(p), "f"(v));
}
__device__ __forceinline__ void cpasync16(unsigned saddr, const void* gptr) {
    asm volatile("cp.async.cg.shared.global [%0], [%1], 16;" :: "r"(saddr), "l"(gptr));
}
__device__ __forceinline__ void cp_commit() {
    asm volatile("cp.async.commit_group;");
}
template <int N>
__device__ __forceinline__ void cp_wait() {
    asm volatile("cp.async.wait_group %0;" :: "n"(N));
}
__device__ __forceinline__ float tanh_acc(float x) {
    float ax = fabsf(x);
    float u  = expm1f(-2.0f * ax);
    float r  = -u / (2.0f + u);
    return x >= 0.0f ? r : -r;
}
__device__ __forceinline__ uint32_t smem_u32(const void* p) {
    uint32_t a;
    asm("{ .reg .u64 t; cvta.to.shared.u64 t, %1; cvt.u32.u64 %0, t; }"
        : "=r"(a) : "l"(p));
    return a;
}

// ---------------- mma.sync helpers (sm_80+ path, compiles at compute_103) ---
__device__ __forceinline__ void ldsm_x4(uint32_t& r0, uint32_t& r1,
                                        uint32_t& r2, uint32_t& r3, uint32_t a) {
    asm volatile("ldmatrix.sync.aligned.m8n8.x4.shared.b16 {%0,%1,%2,%3}, [%4];"
                 : "=r"(r0), "=r"(r1), "=r"(r2), "=r"(r3) : "r"(a));
}
__device__ __forceinline__ void mma16816(float* c, const uint32_t* a, const uint32_t* b) {
    asm volatile("mma.sync.aligned.m16n8k16.row.col.f32.bf16.bf16.f32 "
                 "{%0,%1,%2,%3}, {%4,%5,%6,%7}, {%8,%9}, {%0,%1,%2,%3};"
                 : "+f"(c[0]), "+f"(c[1]), "+f"(c[2]), "+f"(c[3])
                 : "r"(a[0]), "r"(a[1]), "r"(a[2]), "r"(a[3]), "r"(b[0]), "r"(b[1]));
}
__device__ __forceinline__ unsigned swz(unsigned o) { return o ^ ((o >> 3) & 0x70u); }

// ---------------- packing kernels ------------------------------------------
__global__ void pack0(const float* __restrict__ Wh0, const float* __restrict__ Wo0,
                      const float* __restrict__ bh0, const float* __restrict__ bo0)
{
    int idx = blockIdx.x * blockDim.x + threadIdx.x;
    if (idx >= DD * 1024) return;
    int k = idx >> 10, n = idx & 1023;
    bool hc = n < HH;
    int c = hc ? n : n - HH;
    g_W0r[idx] = hc ? Wh0[(DD + k) * HH + c] : Wo0[(DD + k) * DD + c];
    if (idx < 1024) g_b0[idx] = hc ? bh0[c] : bo0[c];
}

__device__ __forceinline__ void split_bf16(float v, __nv_bfloat16* hi, __nv_bfloat16* lo) {
    __nv_bfloat16 h = __float2bfloat16(v);
    *hi = h;
    *lo = __float2bfloat16(v - __bfloat162float(h));
}

__global__ void pack_x(const float* __restrict__ x) {
    size_t idx = (size_t)blockIdx.x * blockDim.x + threadIdx.x;
    if (idx >= (size_t)16384 * 512) return;
    int m = (int)(idx >> 9), k = (int)(idx & 511);
    int b = m & 63, t = m >> 6;
    split_bf16(x[(size_t)b * (TT * DD) + (size_t)t * DD + k], &g_xh[idx], &g_xl[idx]);
}

__global__ void pack_w0(const float* __restrict__ Wh0, const float* __restrict__ Wo0) {
    int idx = blockIdx.x * blockDim.x + threadIdx.x;
    if (idx >= 1024 * 512) return;
    int n = idx >> 9, k = idx & 511;
    float v = (n < 512) ? Wh0[k * 512 + n] : Wo0[k * 512 + (n - 512)];
    split_bf16(v, &g_w0h[idx], &g_w0l[idx]);
}

__global__ void pack_w1(const float* __restrict__ Wo1) {
    int idx = blockIdx.x * blockDim.x + threadIdx.x;
    if (idx >= 512 * 1024) return;
    int n = idx >> 10, k = idx & 1023;
    split_bf16(Wo1[k * 512 + n], &g_w1h[idx], &g_w1l[idx]);
}

__global__ void pack_a1() {
    size_t idx = (size_t)blockIdx.x * blockDim.x + threadIdx.x;
    if (idx >= (size_t)16384 * 1024) return;
    int m = (int)(idx >> 10), k = (int)(idx & 1023);
    int b = m & 63, t = m >> 6;
    float v = (k < 512) ? g_o0T[t][k * 64 + b] : g_h1T[t][(k - 512) * 64 + b];
    split_bf16(v, &g_a1h[idx], &g_a1l[idx]);
}

__global__ void init_state(const float* __restrict__ enc) {
    int idx = blockIdx.x * blockDim.x + threadIdx.x;
    if (idx < HH * BB) {
        int k = idx >> 6, b = idx & 63;
        g_h0T[0][k * 64 + b] = enc[b * HH + k];
        g_h1T[0][idx] = 0.0f;
    }
    if (idx == 0) g_bar = 0u;
}

// ---------------- split-bf16 GEMM via mma.sync -------------------------------
// mode 0: P0[m, n] = x[m,:] @ W0x[:, n]          (M=16384, N=1024, K=512)
// mode 1: out = tanh(A1 @ Wo1 + bo1), transposed (M=16384, N=512,  K=1024)
// CTA tile 128m x 64n; 8 warps (4m x 2n) of 32x32. K in 64-chunks, dbl-buffered.
// SMEM/buf: Ahi 16K | Alo 16K | Bhi 8K | Blo 8K = 48K; x2 = 96 KB. SW128 rows.
// D = Ahi*Bhi + Ahi*Blo + Alo*Bhi (fp32 accum in registers).
__global__ void __launch_bounds__(256)
gemm_mma(int mode, const float* __restrict__ bias, float* __restrict__ outp)
{
    extern __shared__ __align__(16) char smem[];
    const unsigned sb = smem_u32(smem);
    const int tid = threadIdx.x;
    const int wid = tid >> 5, ln = tid & 31;

    const __nv_bfloat16* Ah = mode ? g_a1h : g_xh;
    const __nv_bfloat16* Al = mode ? g_a1l : g_xl;
    const __nv_bfloat16* Bh = mode ? g_w1h : g_w0h;
    const __nv_bfloat16* Bl = mode ? g_w1l : g_w0l;
    const int Kf  = mode ? 1024 : 512;
    const int nch = Kf >> 6;
    const int Nf  = mode ? 512 : 1024;

    const int n0 = blockIdx.x * 64;
    const int m0 = blockIdx.y * 128;

    const int wm = (wid & 3) * 32;   // warp m offset within CTA tile
    const int wn = (wid >> 2) * 32;  // warp n offset

    // stage chunk c into buffer buf
    auto stage = [&](int c, int buf) {
        const unsigned base = sb + (unsigned)buf * 49152u;
        const int kc = c * 64;
        // A: hi (i 0..3) then lo (i 4..7): 1024 16B ops each
#pragma unroll
        for (int i = 0; i < 8; ++i) {
            int idx = tid + (i & 3) * 256;         // 0..1023
            int row = idx >> 3, seg = idx & 7;
            const __nv_bfloat16* s = (i < 4 ? Ah : Al) + (size_t)(m0 + row) * Kf + kc + seg * 8;
            unsigned dst = base + (i < 4 ? 0u : 16384u) + swz((unsigned)(row * 128 + seg * 16));
            cpasync16(dst, s);
        }
        // B: hi (i 0..1), lo (i 2..3): 512 ops each
#pragma unroll
        for (int i = 0; i < 4; ++i) {
            int idx = tid + (i & 1) * 256;         // 0..511
            int row = idx >> 3, seg = idx & 7;
            const __nv_bfloat16* s = (i < 2 ? Bh : Bl) + (size_t)(n0 + row) * Kf + kc + seg * 8;
            unsigned dst = base + (i < 2 ? 32768u : 40960u) + swz((unsigned)(row * 128 + seg * 16));
            cpasync16(dst, s);
        }
        cp_commit();
    };

    float C[2][4][4];
#pragma unroll
    for (int i = 0; i < 2; ++i)
#pragma unroll
        for (int j = 0; j < 4; ++j)
#pragma unroll
            for (int q = 0; q < 4; ++q) C[i][j][q] = 0.0f;

    stage(0, 0);
    for (int c = 0; c < nch; ++c) {
        if (c + 1 < nch) { stage(c + 1, (c + 1) & 1); cp_wait<1>(); }
        else             { cp_wait<0>(); }
        __syncthreads();
        const unsigned base = sb + (unsigned)(c & 1) * 49152u;

#pragma unroll
        for (int ks = 0; ks < 4; ++ks) {
            // A fragments: per m16 tile mi, x4 covers (m0..15, k0|k8)
            uint32_t ah[2][4], al[2][4];
#pragma unroll
            for (int mi = 0; mi < 2; ++mi) {
                int m = wm + mi * 16 + (ln & 15);
                int kb = ks * 2 + (ln >> 4);
                unsigned off = swz((unsigned)(m * 128 + kb * 16));
                ldsm_x4(ah[mi][0], ah[mi][1], ah[mi][2], ah[mi][3], base + off);
                ldsm_x4(al[mi][0], al[mi][1], al[mi][2], al[mi][3], base + 16384u + off);
            }
            // B fragments: per x4 j covers n-tiles 2j, 2j+1 (b0,b1 each)
            uint32_t bh[4][2], bl[4][2];
#pragma unroll
            for (int j = 0; j < 2; ++j) {
                int n = wn + j * 16 + ((ln >= 16) ? 8 : 0) + (ln & 7);
                int kb = ks * 2 + ((ln >> 3) & 1);
                unsigned off = swz((unsigned)(n * 128 + kb * 16));
                uint32_t r0, r1, r2, r3;
                ldsm_x4(r0, r1, r2, r3, base + 32768u + off);
                bh[2 * j][0] = r0; bh[2 * j][1] = r1;
                bh[2 * j + 1][0] = r2; bh[2 * j + 1][1] = r3;
                ldsm_x4(r0, r1, r2, r3, base + 40960u + off);
                bl[2 * j][0] = r0; bl[2 * j][1] = r1;
                bl[2 * j + 1][0] = r2; bl[2 * j + 1][1] = r3;
            }
#pragma unroll
            for (int mi = 0; mi < 2; ++mi)
#pragma unroll
                for (int ni = 0; ni < 4; ++ni) {
                    mma16816(C[mi][ni], ah[mi], bh[ni]);
                    mma16816(C[mi][ni], ah[mi], bl[ni]);
                    mma16816(C[mi][ni], al[mi], bh[ni]);
                }
        }
        __syncthreads();
    }

    // epilogue
    const int grp = ln >> 2, tg = ln & 3;
#pragma unroll
    for (int mi = 0; mi < 2; ++mi) {
#pragma unroll
        for (int ni = 0; ni < 4; ++ni) {
            const int n_g = n0 + wn + ni * 8 + tg * 2;
            const int mg0 = m0 + wm + mi * 16 + grp;
            const int mg1 = mg0 + 8;
            if (mode == 0) {
                *(float2*)(g_P0 + (size_t)mg0 * 1024 + n_g) =
                    make_float2(C[mi][ni][0], C[mi][ni][1]);
                *(float2*)(g_P0 + (size_t)mg1 * 1024 + n_g) =
                    make_float2(C[mi][ni][2], C[mi][ni][3]);
            } else {
                float2 bb = *(const float2*)(bias + n_g);
                int t0 = mg0 >> 6, b0v = mg0 & 63;
                int t1 = mg1 >> 6, b1v = mg1 & 63;
                *(float2*)(outp + ((size_t)b0v * TT + t0) * 512 + n_g) =
                    make_float2(tanh_acc(C[mi][ni][0] + bb.x),
                                tanh_acc(C[mi][ni][1] + bb.y));
                *(float2*)(outp + ((size_t)b1v * TT + t1) * 512 + n_g) =
                    make_float2(tanh_acc(C[mi][ni][2] + bb.x),
                                tanh_acc(C[mi][ni][3] + bb.y));
            }
        }
    }
}

// ---------------- fused pipelined scan (r15 champion, verbatim) -------------
__global__ __launch_bounds__(256)
void scan_fused(const float* __restrict__ Wh1, const float* __restrict__ bh1)
{
    extern __shared__ __align__(16) float sm[];
    float* Ws   = sm;            // 8192 floats
    float* stg0 = sm + 8192;     // 16384 floats
    float* stg1 = sm + 24576;    // 16384 floats
    ull*  redq  = (ull*)(sm + 40960); // 4224 ull = 33 KB

    const int tid = threadIdx.x;
    const int bx  = blockIdx.x;
    const int w   = tid >> 5, ln = tid & 31;
    const int rr  = tid >> 2;
    const int jj  = (tid & 3) << 1;
    const ull* wsq = (const ull*)Ws;

    const unsigned s0addr = (unsigned)__cvta_generic_to_shared(stg0);
    const unsigned s1addr = (unsigned)__cvta_generic_to_shared(stg1);

    if (bx < 64) {
        // ================= A: layer-0 recurrent part =================
        const int n0 = bx * 16;
        for (int i = tid; i < 512 * 16; i += 256) {
            int k = i >> 4, j = i & 15;
            Ws[i] = g_W0r[k * 1024 + n0 + j];
        }
        float bA00 = g_b0[n0 + jj],     bA01 = g_b0[n0 + jj + 1];
        float bA10 = g_b0[n0 + 8 + jj], bA11 = g_b0[n0 + 8 + jj + 1];
        const int cA = jj >> 1;
        const int cB = cA + 4;
        __syncthreads();

        for (int r = 0; r < TT; ++r) {
            float2 p0 = ldcg2(&g_P0[((size_t)r * 64 + rr) * 1024 + n0 + jj]);
            float2 p1 = ldcg2(&g_P0[((size_t)r * 64 + rr) * 1024 + n0 + 8 + jj]);
            const float* hsrc = g_h0T[r & 1];

#pragma unroll
            for (int i = 0; i < 8; ++i)
                cpasync16(s0addr + (tid + i * 256) * 16, hsrc + (tid + i * 256) * 4);
            cp_commit();

            ull a0[8], a1[8];
#pragma unroll
            for (int q = 0; q < 8; ++q) { a0[q] = 0ull; a1[q] = 0ull; }

#pragma unroll
            for (int c = 0; c < 4; ++c) {
                if (c < 3) {
                    const unsigned dst = (c & 1) ? s0addr : s1addr;
                    const float* src = hsrc + (c + 1) * 8192;
#pragma unroll
                    for (int i = 0; i < 8; ++i)
                        cpasync16(dst + (tid + i * 256) * 16, src + (tid + i * 256) * 4);
                    cp_commit();
                    cp_wait<1>();
                } else {
                    cp_wait<0>();
                }
                __syncthreads();
                const float* hb = (c & 1) ? stg1 : stg0;
                const int kg = c * 128 + w * 16;
#pragma unroll 4
                for (int kk = 0; kk < 16; ++kk) {
                    float2 h2 = *(const float2*)(hb + (w * 16 + kk) * 64 + 2 * ln);
                    ull hx = dup2(h2.x), hy = dup2(h2.y);
                    const ulonglong2* wp = (const ulonglong2*)(wsq + (size_t)(kg + kk) * 8);
                    ulonglong2 u0 = wp[0], u1 = wp[1], u2 = wp[2], u3 = wp[3];
                    a0[0] = ffma2(hx, u0.x, a0[0]); a1[0] = ffma2(hy, u0.x, a1[0]);
                    a0[1] = ffma2(hx, u0.y, a0[1]); a1[1] = ffma2(hy, u0.y, a1[1]);
                    a0[2] = ffma2(hx, u1.x, a0[2]); a1[2] = ffma2(hy, u1.x, a1[2]);
                    a0[3] = ffma2(hx, u1.y, a0[3]); a1[3] = ffma2(hy, u1.y, a1[3]);
                    a0[4] = ffma2(hx, u2.x, a0[4]); a1[4] = ffma2(hy, u2.x, a1[4]);
                    a0[5] = ffma2(hx, u2.y, a0[5]); a1[5] = ffma2(hy, u2.y, a1[5]);
                    a0[6] = ffma2(hx, u3.x, a0[6]); a1[6] = ffma2(hy, u3.x, a1[6]);
                    a0[7] = ffma2(hx, u3.y, a0[7]); a1[7] = ffma2(hy, u3.y, a1[7]);
                }
                __syncthreads();
            }

#pragma unroll
            for (int c = 0; c < 8; ++c)
                *(ulonglong2*)&redq[(w * 8 + c) * 66 + 2 * ln] =
                    make_ulonglong2(a0[c], a1[c]);
            __syncthreads();

            float s0 = p0.x + bA00, s1 = p0.y + bA01;
            float s2 = p1.x + bA10, s3 = p1.y + bA11;
#pragma unroll
            for (int ww = 0; ww < 8; ++ww) {
                float2 t0 = unpk(redq[(ww * 8 + cA) * 66 + rr]);
                float2 t1 = unpk(redq[(ww * 8 + cB) * 66 + rr]);
                s0 += t0.x; s1 += t0.y;
                s2 += t1.x; s3 += t1.y;
            }
            s0 = tanh_acc(s0); s1 = tanh_acc(s1);
            s2 = tanh_acc(s2); s3 = tanh_acc(s3);

            const int ca = n0 + jj, cb = n0 + 8 + jj;
            if (n0 < 512) {
                float* dst = g_h0T[(r + 1) & 1];
                stcg(dst + (ca)     * 64 + rr, s0);
                stcg(dst + (ca + 1) * 64 + rr, s1);
                stcg(dst + (cb)     * 64 + rr, s2);
                stcg(dst + (cb + 1) * 64 + rr, s3);
            } else {
                float* dst = g_o0T[r];
                stcg(dst + (ca - 512) * 64 + rr, s0);
                stcg(dst + (ca - 511) * 64 + rr, s1);
                stcg(dst + (cb - 512) * 64 + rr, s2);
                stcg(dst + (cb - 511) * 64 + rr, s3);
            }
            __syncthreads();

            if (r < TT - 1) {
                if (tid == 0) {
                    asm volatile("red.release.gpu.global.add.u32 [%0], 1;"
                                 :: "l"(&g_bar) : "memory");
                    const unsigned tgt = (unsigned)(r + 1) * 128u;
                    unsigned v;
                    do {
                        asm volatile("ld.acquire.gpu.global.u32 %0, [%1];"
                                     : "=r"(v) : "l"(&g_bar) : "memory");
                    } while (v < tgt);
                }
                __syncthreads();
            }
        }
    } else {
        // ================= B: layer-1 hidden chain (one step behind) =========
        const int c0 = (bx - 64) * 8;
        for (int i = tid; i < 1024 * 8; i += 256) {
            int k = i >> 3, j = i & 7;
            Ws[i] = Wh1[k * 512 + c0 + j];
        }
        const float b0v = bh1[c0 + jj], b1v = bh1[c0 + jj + 1];
        const int cR = jj >> 1;
        __syncthreads();

        for (int r = 0; r < TT; ++r) {
            if (r >= 1) {
                const int t1 = r - 1;
                const float* srcs[4] = {
                    g_o0T[t1], g_o0T[t1] + 16384,
                    g_h1T[t1], g_h1T[t1] + 16384
                };
#pragma unroll
                for (int i = 0; i < 16; ++i)
                    cpasync16(s0addr + (unsigned)((tid + i * 256) * 16),
                              srcs[0] + (tid + i * 256) * 4);
                cp_commit();

                ull a0[4], a1[4];
#pragma unroll
                for (int q = 0; q < 4; ++q) { a0[q] = 0ull; a1[q] = 0ull; }

#pragma unroll
                for (int c = 0; c < 4; ++c) {
                    if (c < 3) {
                        const unsigned dst = (c & 1) ? s0addr : s1addr;
                        const float* src = srcs[c + 1];
#pragma unroll
                        for (int i = 0; i < 16; ++i)
                            cpasync16(dst + (unsigned)((tid + i * 256) * 16),
                                      src + (tid + i * 256) * 4);
                        cp_commit();
                        cp_wait<1>();
                    } else {
                        cp_wait<0>();
                    }
                    __syncthreads();
                    const float* hb = (c & 1) ? stg1 : stg0;
                    const int kg = c * 256 + w * 32;
#pragma unroll 4
                    for (int q = 0; q < 32; ++q) {
                        float2 h2 = *(const float2*)(hb + (w * 32 + q) * 64 + 2 * ln);
                        ull hx = dup2(h2.x), hy = dup2(h2.y);
                        const ulonglong2* wp = (const ulonglong2*)(wsq + (size_t)(kg + q) * 4);
                        ulonglong2 u0 = wp[0], u1 = wp[1];
                        a0[0] = ffma2(hx, u0.x, a0[0]); a1[0] = ffma2(hy, u0.x, a1[0]);
                        a0[1] = ffma2(hx, u0.y, a0[1]); a1[1] = ffma2(hy, u0.y, a1[1]);
                        a0[2] = ffma2(hx, u1.x, a0[2]); a1[2] = ffma2(hy, u1.x, a1[2]);
                        a0[3] = ffma2(hx, u1.y, a0[3]); a1[3] = ffma2(hy, u1.y, a1[3]);
                    }
                    __syncthreads();
                }
#pragma unroll
                for (int q = 0; q < 4; ++q)
                    *(ulonglong2*)&redq[(w * 4 + q) * 66 + 2 * ln] =
                        make_ulonglong2(a0[q], a1[q]);
                __syncthreads();
                float s0 = b0v, s1 = b1v;
#pragma unroll
                for (int ww = 0; ww < 8; ++ww) {
                    float2 t2 = unpk(redq[(ww * 4 + cR) * 66 + rr]);
                    s0 += t2.x; s1 += t2.y;
                }
                s0 = tanh_acc(s0);
                s1 = tanh_acc(s1);
                float* dst = g_h1T[r];
                stcg(dst + (c0 + jj)     * 64 + rr, s0);
                stcg(dst + (c0 + jj + 1) * 64 + rr, s1);
                __syncthreads();
            }
            if (r < TT - 1) {
                if (tid == 0) {
                    asm volatile("red.release.gpu.global.add.u32 [%0], 1;"
                                 :: "l"(&g_bar) : "memory");
                    const unsigned tgt = (unsigned)(r + 1) * 128u;
                    unsigned v;
                    do {
                        asm volatile("ld.acquire.gpu.global.u32 %0, [%1];"
                                     : "=r"(v) : "l"(&g_bar) : "memory");
                    } while (v < tgt);
                }
                __syncthreads();
            }
        }
    }
}

// ---------------- launch ---------------------------------------------------
extern "C" void kernel_launch(void* const* d_in, const int* in_sizes, int n_in,
                              void* d_out, int out_size)
{
    const float* x   = (const float*)d_in[0];
    const float* enc = (const float*)d_in[1];
    const float* Wh0 = (const float*)d_in[2];
    const float* bh0 = (const float*)d_in[3];
    const float* Wo0 = (const float*)d_in[4];
    const float* bo0 = (const float*)d_in[5];
    const float* Wh1 = (const float*)d_in[6];
    const float* bh1 = (const float*)d_in[7];
    const float* Wo1 = (const float*)d_in[8];
    const float* bo1 = (const float*)d_in[9];
    float* out = (float*)d_out;

    static int attr_set = 0;
    if (!attr_set) {
        cudaFuncSetAttribute(scan_fused,
                             cudaFuncAttributeMaxDynamicSharedMemorySize, 197632);
        cudaFuncSetAttribute(gemm_mma,
                             cudaFuncAttributeMaxDynamicSharedMemorySize, 98304);
        attr_set = 1;
    }

    pack0<<<(DD * 1024 + 255) / 256, 256>>>(Wh0, Wo0, bh0, bo0);
    pack_x<<<32768, 256>>>(x);
    pack_w0<<<2048, 256>>>(Wh0, Wo0);
    pack_w1<<<2048, 256>>>(Wo1);
    init_state<<<(HH * BB + 255) / 256, 256>>>(enc);

    gemm_mma<<<dim3(16, 128), 256, 98304>>>(0, nullptr, nullptr);   // P0
    scan_fused<<<128, 256, 197632>>>(Wh1, bh1);
    pack_a1<<<65536, 256>>>();
    gemm_mma<<<dim3(8, 128), 256, 98304>>>(1, bo1, out);            // final out
}